// round 2
// baseline (speedup 1.0000x reference)
#include <cuda_runtime.h>
#include <math.h>

// Problem constants
#define BB 2
#define SS 2048
#define EE 1024
#define HH 16
#define DD 64
#define MTOT (BB * SS)   // 4096

// Scratch (static device globals — no dynamic allocation allowed)
__device__ float g_Qh[MTOT * EE];
__device__ float g_Kh[MTOT * EE];
__device__ float g_Vh[MTOT * EE];
__device__ float g_Ctx[MTOT * EE];

// ---------------------------------------------------------------------------
// GEMM: C[M,N] = A[M,K] @ W[N,K]^T + bias[N]
// M=4096, N=1024, K=1024. BM=BN=64, BK=32, 256 threads, 4x4 micro-tile.
// ---------------------------------------------------------------------------
#define BK 32
#define BKP 33  // padded stride

__global__ __launch_bounds__(256) void gemm_bias_kernel(
    const float* __restrict__ A, const float* __restrict__ W,
    const float* __restrict__ bias, float* __restrict__ C,
    int M, int N, int K)
{
    __shared__ float sA[64 * BKP];
    __shared__ float sW[64 * BKP];

    const int tid = threadIdx.x;
    const int tx = tid & 15;        // 0..15 (N direction)
    const int ty = tid >> 4;        // 0..15 (M direction)

    const int row0 = blockIdx.y * 64;
    const int col0 = blockIdx.x * 64;

    float acc[4][4];
#pragma unroll
    for (int i = 0; i < 4; i++)
#pragma unroll
        for (int j = 0; j < 4; j++) acc[i][j] = 0.0f;

    for (int k0 = 0; k0 < K; k0 += BK) {
        // Load A tile 64 x 32 (2048 elems, 8 per thread, coalesced)
#pragma unroll
        for (int l = 0; l < 8; l++) {
            int idx = tid + l * 256;
            int r = idx >> 5;       // /32
            int c = idx & 31;
            sA[r * BKP + c] = A[(row0 + r) * K + k0 + c];
            sW[r * BKP + c] = W[(col0 + r) * K + k0 + c];
        }
        __syncthreads();

#pragma unroll
        for (int kk = 0; kk < BK; kk++) {
            float a[4], b[4];
#pragma unroll
            for (int i = 0; i < 4; i++) a[i] = sA[(ty * 4 + i) * BKP + kk];
#pragma unroll
            for (int j = 0; j < 4; j++) b[j] = sW[(tx * 4 + j) * BKP + kk];
#pragma unroll
            for (int i = 0; i < 4; i++)
#pragma unroll
                for (int j = 0; j < 4; j++) acc[i][j] = fmaf(a[i], b[j], acc[i][j]);
        }
        __syncthreads();
    }

#pragma unroll
    for (int i = 0; i < 4; i++) {
        int r = row0 + ty * 4 + i;
#pragma unroll
        for (int j = 0; j < 4; j++) {
            int c = col0 + tx * 4 + j;
            C[r * N + c] = acc[i][j] + bias[c];
        }
    }
}

// ---------------------------------------------------------------------------
// Flash attention: per (b, h, 64-row Q tile), stream 64-row K/V tiles.
// scores = Q K^T / sqrt(H) = * 0.25, online softmax, O accumulated in regs.
// ---------------------------------------------------------------------------
#define SK_STR 65

__global__ __launch_bounds__(256) void attn_kernel(
    const float* __restrict__ Qh, const float* __restrict__ Kh,
    const float* __restrict__ Vh, float* __restrict__ Ctx)
{
    extern __shared__ float sm[];
    float* sQ = sm;                       // 64*64
    float* sK = sQ + 64 * 64;             // 64*65
    float* sV = sK + 64 * SK_STR;         // 64*64
    float* sS = sV + 64 * 64;             // 64*64
    float* sM = sS + 64 * 64;             // 64
    float* sL = sM + 64;                  // 64
    float* sAl = sL + 64;                 // 64

    const int tid = threadIdx.x;
    const int tx = tid & 15;
    const int ty = tid >> 4;
    const int warp = tid >> 5;
    const int lane = tid & 31;

    const int b = blockIdx.z;
    const int h = blockIdx.y;
    const int q0 = blockIdx.x * 64;

    const int hd = h * DD;

    // Load Q tile (coalesced: 64 consecutive cols per row)
#pragma unroll
    for (int l = 0; l < 16; l++) {
        int idx = tid + l * 256;
        int r = idx >> 6;
        int c = idx & 63;
        sQ[r * 64 + c] = Qh[((size_t)(b * SS + q0 + r)) * EE + hd + c];
    }
    if (tid < 64) { sM[tid] = -INFINITY; sL[tid] = 0.0f; }

    float o[4][4];
#pragma unroll
    for (int i = 0; i < 4; i++)
#pragma unroll
        for (int j = 0; j < 4; j++) o[i][j] = 0.0f;

    __syncthreads();

    for (int kv0 = 0; kv0 < SS; kv0 += 64) {
        // Load K and V tiles
#pragma unroll
        for (int l = 0; l < 16; l++) {
            int idx = tid + l * 256;
            int r = idx >> 6;
            int c = idx & 63;
            size_t g = ((size_t)(b * SS + kv0 + r)) * EE + hd + c;
            sK[r * SK_STR + c] = Kh[g];
            sV[r * 64 + c] = Vh[g];
        }
        __syncthreads();

        // S = Q K^T * 0.25 (each thread: 4x4 of the 64x64 tile)
        float acc[4][4];
#pragma unroll
        for (int i = 0; i < 4; i++)
#pragma unroll
            for (int j = 0; j < 4; j++) acc[i][j] = 0.0f;

#pragma unroll 16
        for (int kk = 0; kk < 64; kk++) {
            float a[4], bb[4];
#pragma unroll
            for (int i = 0; i < 4; i++) a[i] = sQ[(ty * 4 + i) * 64 + kk];
#pragma unroll
            for (int j = 0; j < 4; j++) bb[j] = sK[(tx * 4 + j) * SK_STR + kk];
#pragma unroll
            for (int i = 0; i < 4; i++)
#pragma unroll
                for (int j = 0; j < 4; j++) acc[i][j] = fmaf(a[i], bb[j], acc[i][j]);
        }
#pragma unroll
        for (int i = 0; i < 4; i++)
#pragma unroll
            for (int j = 0; j < 4; j++)
                sS[(ty * 4 + i) * 64 + tx * 4 + j] = acc[i][j] * 0.25f;
        __syncthreads();

        // Online softmax: warp w owns rows [w*8, w*8+8); lane covers cols lane, lane+32
#pragma unroll
        for (int rr = 0; rr < 8; rr++) {
            int r = warp * 8 + rr;
            float v1 = sS[r * 64 + lane];
            float v2 = sS[r * 64 + lane + 32];
            float mx = fmaxf(v1, v2);
#pragma unroll
            for (int off = 16; off > 0; off >>= 1)
                mx = fmaxf(mx, __shfl_xor_sync(0xFFFFFFFFu, mx, off));
            float mOld = sM[r];
            float mNew = fmaxf(mOld, mx);
            float p1 = __expf(v1 - mNew);
            float p2 = __expf(v2 - mNew);
            sS[r * 64 + lane] = p1;
            sS[r * 64 + lane + 32] = p2;
            float sum = p1 + p2;
#pragma unroll
            for (int off = 16; off > 0; off >>= 1)
                sum += __shfl_xor_sync(0xFFFFFFFFu, sum, off);
            if (lane == 0) {
                float al = __expf(mOld - mNew);
                sAl[r] = al;
                sL[r] = sL[r] * al + sum;
                sM[r] = mNew;
            }
        }
        __syncthreads();

        // O = alpha*O + P @ V
#pragma unroll
        for (int i = 0; i < 4; i++) {
            float al = sAl[ty * 4 + i];
#pragma unroll
            for (int j = 0; j < 4; j++) o[i][j] *= al;
        }
#pragma unroll 16
        for (int kk = 0; kk < 64; kk++) {
            float p[4], vv[4];
#pragma unroll
            for (int i = 0; i < 4; i++) p[i] = sS[(ty * 4 + i) * 64 + kk];
#pragma unroll
            for (int j = 0; j < 4; j++) vv[j] = sV[kk * 64 + tx * 4 + j];
#pragma unroll
            for (int i = 0; i < 4; i++)
#pragma unroll
                for (int j = 0; j < 4; j++) o[i][j] = fmaf(p[i], vv[j], o[i][j]);
        }
        __syncthreads();  // protect sK/sV/sS before next tile load
    }

    // Epilogue: O / l -> Ctx[b, q, h*64 + d]
#pragma unroll
    for (int i = 0; i < 4; i++) {
        int r = ty * 4 + i;
        float invl = 1.0f / sL[r];
#pragma unroll
        for (int j = 0; j < 4; j++) {
            Ctx[((size_t)(b * SS + q0 + r)) * EE + hd + tx * 4 + j] = o[i][j] * invl;
        }
    }
}

// ---------------------------------------------------------------------------
// Launch
// ---------------------------------------------------------------------------
extern "C" void kernel_launch(void* const* d_in, const int* in_sizes, int n_in,
                              void* d_out, int out_size)
{
    const float* q  = (const float*)d_in[0];
    const float* k  = (const float*)d_in[1];
    const float* v  = (const float*)d_in[2];
    const float* Wq = (const float*)d_in[3];
    const float* bq = (const float*)d_in[4];
    const float* Wk = (const float*)d_in[5];
    const float* bk = (const float*)d_in[6];
    const float* Wv = (const float*)d_in[7];
    const float* bv = (const float*)d_in[8];
    const float* Wo = (const float*)d_in[9];
    const float* bo = (const float*)d_in[10];
    float* out = (float*)d_out;

    float* Qh;  cudaGetSymbolAddress((void**)&Qh,  g_Qh);
    float* Kh;  cudaGetSymbolAddress((void**)&Kh,  g_Kh);
    float* Vh;  cudaGetSymbolAddress((void**)&Vh,  g_Vh);
    float* Ctx; cudaGetSymbolAddress((void**)&Ctx, g_Ctx);

    const int smem_attn = (64 * 64 * 3 + 64 * SK_STR + 3 * 64) * (int)sizeof(float);
    cudaFuncSetAttribute(attn_kernel, cudaFuncAttributeMaxDynamicSharedMemorySize,
                         smem_attn);

    dim3 gemm_grid(EE / 64, MTOT / 64);   // (16, 64)
    gemm_bias_kernel<<<gemm_grid, 256>>>(q, Wq, bq, Qh, MTOT, EE, EE);
    gemm_bias_kernel<<<gemm_grid, 256>>>(k, Wk, bk, Kh, MTOT, EE, EE);
    gemm_bias_kernel<<<gemm_grid, 256>>>(v, Wv, bv, Vh, MTOT, EE, EE);

    dim3 attn_grid(SS / 64, HH, BB);      // (32, 16, 2)
    attn_kernel<<<attn_grid, 256, smem_attn>>>(Qh, Kh, Vh, Ctx);

    gemm_bias_kernel<<<gemm_grid, 256>>>(Ctx, Wo, bo, out, MTOT, EE, EE);
}

// round 3
// speedup vs baseline: 2.4627x; 2.4627x over previous
#include <cuda_runtime.h>
#include <math.h>
#include <stdint.h>

#define BB 2
#define SS 2048
#define EE 1024
#define HH 16
#define DD 64
#define MTOT (BB * SS)   // 4096

__device__ float g_Qh[MTOT * EE];
__device__ float g_Kh[MTOT * EE];
__device__ float g_Vh[MTOT * EE];
__device__ float g_Ctx[MTOT * EE];

// ---------------------------------------------------------------------------
// tf32 helpers
// ---------------------------------------------------------------------------
__device__ __forceinline__ uint32_t f2tf(float f) {
    uint32_t u;
    asm("cvt.rna.tf32.f32 %0, %1;" : "=r"(u) : "f"(f));
    return u;
}

__device__ __forceinline__ void mma8(float* c, const uint32_t* a, const uint32_t* b) {
    asm volatile(
        "mma.sync.aligned.m16n8k8.row.col.f32.tf32.tf32.f32 "
        "{%0,%1,%2,%3},{%4,%5,%6,%7},{%8,%9},{%0,%1,%2,%3};"
        : "+f"(c[0]), "+f"(c[1]), "+f"(c[2]), "+f"(c[3])
        : "r"(a[0]), "r"(a[1]), "r"(a[2]), "r"(a[3]), "r"(b[0]), "r"(b[1]));
}

// ---------------------------------------------------------------------------
// GEMM: C[M,N] = A[M,K] @ W[N,K]^T + bias[N]   (tf32 tensor-core)
// Block tile 128x128, BK=32, 256 threads (8 warps, 4x2 warp grid, 32x64/warp)
// ---------------------------------------------------------------------------
#define GKP 36   // padded smem stride: (36*g + tig) % 32 = (4g + tig) -> conflict-free frags

__global__ __launch_bounds__(256, 2) void gemm_tc(
    const float* __restrict__ A, const float* __restrict__ W,
    const float* __restrict__ bias, float* __restrict__ C,
    int M, int N, int K)
{
    __shared__ uint32_t sA[128 * GKP];
    __shared__ uint32_t sW[128 * GKP];

    const int tid = threadIdx.x;
    const int lane = tid & 31, warp = tid >> 5;
    const int wm = warp >> 1;   // 0..3 -> 32 rows each
    const int wn = warp & 1;    // 0..1 -> 64 cols each
    const int g = lane >> 2, tig = lane & 3;

    const int row0 = blockIdx.y * 128;
    const int col0 = blockIdx.x * 128;

    float acc[2][8][4];
#pragma unroll
    for (int i = 0; i < 2; i++)
#pragma unroll
        for (int j = 0; j < 8; j++)
#pragma unroll
            for (int l = 0; l < 4; l++) acc[i][j][l] = 0.0f;

    for (int k0 = 0; k0 < K; k0 += 32) {
#pragma unroll
        for (int p = 0; p < 4; p++) {
            int i = tid + p * 256;       // 0..1023 float4 slots
            int r = i >> 3;              // 8 float4 per 32-col row
            int c = (i & 7) << 2;
            float4 va = *(const float4*)&A[(size_t)(row0 + r) * K + k0 + c];
            sA[r * GKP + c + 0] = f2tf(va.x);
            sA[r * GKP + c + 1] = f2tf(va.y);
            sA[r * GKP + c + 2] = f2tf(va.z);
            sA[r * GKP + c + 3] = f2tf(va.w);
            float4 vw = *(const float4*)&W[(size_t)(col0 + r) * K + k0 + c];
            sW[r * GKP + c + 0] = f2tf(vw.x);
            sW[r * GKP + c + 1] = f2tf(vw.y);
            sW[r * GKP + c + 2] = f2tf(vw.z);
            sW[r * GKP + c + 3] = f2tf(vw.w);
        }
        __syncthreads();

#pragma unroll
        for (int ks = 0; ks < 4; ks++) {
            uint32_t af[2][4], bf[8][2];
#pragma unroll
            for (int mt = 0; mt < 2; mt++) {
                int rb = wm * 32 + mt * 16;
                af[mt][0] = sA[(rb + g) * GKP + ks * 8 + tig];
                af[mt][1] = sA[(rb + 8 + g) * GKP + ks * 8 + tig];
                af[mt][2] = sA[(rb + g) * GKP + ks * 8 + tig + 4];
                af[mt][3] = sA[(rb + 8 + g) * GKP + ks * 8 + tig + 4];
            }
#pragma unroll
            for (int nt = 0; nt < 8; nt++) {
                int cb = wn * 64 + nt * 8;
                bf[nt][0] = sW[(cb + g) * GKP + ks * 8 + tig];
                bf[nt][1] = sW[(cb + g) * GKP + ks * 8 + tig + 4];
            }
#pragma unroll
            for (int mt = 0; mt < 2; mt++)
#pragma unroll
                for (int nt = 0; nt < 8; nt++)
                    mma8(acc[mt][nt], af[mt], bf[nt]);
        }
        __syncthreads();
    }

#pragma unroll
    for (int mt = 0; mt < 2; mt++) {
        int r = row0 + wm * 32 + mt * 16;
#pragma unroll
        for (int nt = 0; nt < 8; nt++) {
            int c = col0 + wn * 64 + nt * 8 + 2 * tig;
            float b0 = bias[c], b1 = bias[c + 1];
            C[(size_t)(r + g) * N + c]         = acc[mt][nt][0] + b0;
            C[(size_t)(r + g) * N + c + 1]     = acc[mt][nt][1] + b1;
            C[(size_t)(r + 8 + g) * N + c]     = acc[mt][nt][2] + b0;
            C[(size_t)(r + 8 + g) * N + c + 1] = acc[mt][nt][3] + b1;
        }
    }
}

// ---------------------------------------------------------------------------
// Flash attention, tensor-core QK^T and PV.
// Block = (b, h, 64-row Q tile), 256 threads, 8 warps (2x4 warp grid, 32x16).
// ---------------------------------------------------------------------------
#define SQP 68   // stride for sQ/sK/sS: (68g + tig) % 32 = (4g + tig) distinct
#define SVP 72   // stride for sV:       (72*tig + g) % 32 = (8*tig + g) distinct

__global__ __launch_bounds__(256, 2) void attn_tc(
    const float* __restrict__ Qh, const float* __restrict__ Kh,
    const float* __restrict__ Vh, float* __restrict__ Ctx)
{
    extern __shared__ uint32_t smu[];
    uint32_t* sQ = smu;                  // 64*68
    uint32_t* sK = sQ + 64 * SQP;        // 64*68
    uint32_t* sV = sK + 64 * SQP;        // 64*72
    float* sS = (float*)(sV + 64 * SVP); // 64*68 (fp32)
    float* sM = sS + 64 * SQP;
    float* sL = sM + 64;
    float* sAl = sL + 64;

    const int tid = threadIdx.x;
    const int lane = tid & 31, warp = tid >> 5;
    const int wm = warp >> 2;   // 0..1 -> 32 q-rows
    const int wn = warp & 3;    // 0..3 -> 16 cols
    const int g = lane >> 2, tig = lane & 3;

    const int b = blockIdx.z, h = blockIdx.y, q0 = blockIdx.x * 64;
    const int hd = h * DD;

    // Load Q tile (convert to tf32 once)
#pragma unroll
    for (int p = 0; p < 4; p++) {
        int i = tid + p * 256;
        int r = i >> 4, c = (i & 15) << 2;
        float4 v = *(const float4*)&Qh[(size_t)(b * SS + q0 + r) * EE + hd + c];
        sQ[r * SQP + c + 0] = f2tf(v.x);
        sQ[r * SQP + c + 1] = f2tf(v.y);
        sQ[r * SQP + c + 2] = f2tf(v.z);
        sQ[r * SQP + c + 3] = f2tf(v.w);
    }
    if (tid < 64) { sM[tid] = -INFINITY; sL[tid] = 0.0f; }

    float o[2][2][4];
#pragma unroll
    for (int mt = 0; mt < 2; mt++)
#pragma unroll
        for (int nt = 0; nt < 2; nt++)
#pragma unroll
            for (int l = 0; l < 4; l++) o[mt][nt][l] = 0.0f;

    __syncthreads();

    for (int kv0 = 0; kv0 < SS; kv0 += 64) {
        // Load K and V tiles
#pragma unroll
        for (int p = 0; p < 4; p++) {
            int i = tid + p * 256;
            int r = i >> 4, c = (i & 15) << 2;
            size_t gk = (size_t)(b * SS + kv0 + r) * EE + hd + c;
            float4 vk = *(const float4*)&Kh[gk];
            sK[r * SQP + c + 0] = f2tf(vk.x);
            sK[r * SQP + c + 1] = f2tf(vk.y);
            sK[r * SQP + c + 2] = f2tf(vk.z);
            sK[r * SQP + c + 3] = f2tf(vk.w);
            float4 vv = *(const float4*)&Vh[gk];
            sV[r * SVP + c + 0] = f2tf(vv.x);
            sV[r * SVP + c + 1] = f2tf(vv.y);
            sV[r * SVP + c + 2] = f2tf(vv.z);
            sV[r * SVP + c + 3] = f2tf(vv.w);
        }
        __syncthreads();

        // S = Q @ K^T
        float sc[2][2][4];
#pragma unroll
        for (int mt = 0; mt < 2; mt++)
#pragma unroll
            for (int nt = 0; nt < 2; nt++)
#pragma unroll
                for (int l = 0; l < 4; l++) sc[mt][nt][l] = 0.0f;

#pragma unroll
        for (int ks = 0; ks < 8; ks++) {
            uint32_t af[2][4], bf[2][2];
#pragma unroll
            for (int mt = 0; mt < 2; mt++) {
                int rb = wm * 32 + mt * 16;
                af[mt][0] = sQ[(rb + g) * SQP + ks * 8 + tig];
                af[mt][1] = sQ[(rb + 8 + g) * SQP + ks * 8 + tig];
                af[mt][2] = sQ[(rb + g) * SQP + ks * 8 + tig + 4];
                af[mt][3] = sQ[(rb + 8 + g) * SQP + ks * 8 + tig + 4];
            }
#pragma unroll
            for (int nt = 0; nt < 2; nt++) {
                int cb = wn * 16 + nt * 8;
                bf[nt][0] = sK[(cb + g) * SQP + ks * 8 + tig];
                bf[nt][1] = sK[(cb + g) * SQP + ks * 8 + tig + 4];
            }
#pragma unroll
            for (int mt = 0; mt < 2; mt++)
#pragma unroll
                for (int nt = 0; nt < 2; nt++)
                    mma8(sc[mt][nt], af[mt], bf[nt]);
        }

        // Write scaled scores to smem (scale = 1/sqrt(H) = 0.25)
#pragma unroll
        for (int mt = 0; mt < 2; mt++) {
            int rb = wm * 32 + mt * 16;
#pragma unroll
            for (int nt = 0; nt < 2; nt++) {
                int cb = wn * 16 + nt * 8 + 2 * tig;
                sS[(rb + g) * SQP + cb]         = sc[mt][nt][0] * 0.25f;
                sS[(rb + g) * SQP + cb + 1]     = sc[mt][nt][1] * 0.25f;
                sS[(rb + 8 + g) * SQP + cb]     = sc[mt][nt][2] * 0.25f;
                sS[(rb + 8 + g) * SQP + cb + 1] = sc[mt][nt][3] * 0.25f;
            }
        }
        __syncthreads();

        // Online softmax: warp w owns rows [w*8, w*8+8)
#pragma unroll
        for (int rr = 0; rr < 8; rr++) {
            int r = warp * 8 + rr;
            float v1 = sS[r * SQP + lane];
            float v2 = sS[r * SQP + lane + 32];
            float mx = fmaxf(v1, v2);
#pragma unroll
            for (int off = 16; off > 0; off >>= 1)
                mx = fmaxf(mx, __shfl_xor_sync(0xFFFFFFFFu, mx, off));
            float mOld = sM[r];
            float mNew = fmaxf(mOld, mx);
            float p1 = __expf(v1 - mNew);
            float p2 = __expf(v2 - mNew);
            sS[r * SQP + lane] = p1;
            sS[r * SQP + lane + 32] = p2;
            float sum = p1 + p2;
#pragma unroll
            for (int off = 16; off > 0; off >>= 1)
                sum += __shfl_xor_sync(0xFFFFFFFFu, sum, off);
            if (lane == 0) {
                float al = __expf(mOld - mNew);
                sAl[r] = al;
                sL[r] = sL[r] * al + sum;
                sM[r] = mNew;
            }
        }
        __syncthreads();

        // O = alpha * O + P @ V
#pragma unroll
        for (int mt = 0; mt < 2; mt++) {
            int rb = wm * 32 + mt * 16;
            float aA = sAl[rb + g];
            float aB = sAl[rb + 8 + g];
#pragma unroll
            for (int nt = 0; nt < 2; nt++) {
                o[mt][nt][0] *= aA; o[mt][nt][1] *= aA;
                o[mt][nt][2] *= aB; o[mt][nt][3] *= aB;
            }
        }
#pragma unroll
        for (int ks = 0; ks < 8; ks++) {
            uint32_t af[2][4], bf[2][2];
#pragma unroll
            for (int mt = 0; mt < 2; mt++) {
                int rb = wm * 32 + mt * 16;
                af[mt][0] = f2tf(sS[(rb + g) * SQP + ks * 8 + tig]);
                af[mt][1] = f2tf(sS[(rb + 8 + g) * SQP + ks * 8 + tig]);
                af[mt][2] = f2tf(sS[(rb + g) * SQP + ks * 8 + tig + 4]);
                af[mt][3] = f2tf(sS[(rb + 8 + g) * SQP + ks * 8 + tig + 4]);
            }
#pragma unroll
            for (int nt = 0; nt < 2; nt++) {
                int cb = wn * 16 + nt * 8;
                bf[nt][0] = sV[(ks * 8 + tig) * SVP + cb + g];
                bf[nt][1] = sV[(ks * 8 + tig + 4) * SVP + cb + g];
            }
#pragma unroll
            for (int mt = 0; mt < 2; mt++)
#pragma unroll
                for (int nt = 0; nt < 2; nt++)
                    mma8(o[mt][nt], af[mt], bf[nt]);
        }
        __syncthreads();
    }

    // Epilogue: O / l -> Ctx
#pragma unroll
    for (int mt = 0; mt < 2; mt++) {
        int rb = wm * 32 + mt * 16;
        float iA = 1.0f / sL[rb + g];
        float iB = 1.0f / sL[rb + 8 + g];
#pragma unroll
        for (int nt = 0; nt < 2; nt++) {
            int c = hd + wn * 16 + nt * 8 + 2 * tig;
            Ctx[(size_t)(b * SS + q0 + rb + g) * EE + c]         = o[mt][nt][0] * iA;
            Ctx[(size_t)(b * SS + q0 + rb + g) * EE + c + 1]     = o[mt][nt][1] * iA;
            Ctx[(size_t)(b * SS + q0 + rb + 8 + g) * EE + c]     = o[mt][nt][2] * iB;
            Ctx[(size_t)(b * SS + q0 + rb + 8 + g) * EE + c + 1] = o[mt][nt][3] * iB;
        }
    }
}

// ---------------------------------------------------------------------------
// Launch
// ---------------------------------------------------------------------------
extern "C" void kernel_launch(void* const* d_in, const int* in_sizes, int n_in,
                              void* d_out, int out_size)
{
    const float* q  = (const float*)d_in[0];
    const float* k  = (const float*)d_in[1];
    const float* v  = (const float*)d_in[2];
    const float* Wq = (const float*)d_in[3];
    const float* bq = (const float*)d_in[4];
    const float* Wk = (const float*)d_in[5];
    const float* bk = (const float*)d_in[6];
    const float* Wv = (const float*)d_in[7];
    const float* bv = (const float*)d_in[8];
    const float* Wo = (const float*)d_in[9];
    const float* bo = (const float*)d_in[10];
    float* out = (float*)d_out;

    float* Qh;  cudaGetSymbolAddress((void**)&Qh,  g_Qh);
    float* Kh;  cudaGetSymbolAddress((void**)&Kh,  g_Kh);
    float* Vh;  cudaGetSymbolAddress((void**)&Vh,  g_Vh);
    float* Ctx; cudaGetSymbolAddress((void**)&Ctx, g_Ctx);

    const int smem_attn = (64 * SQP * 2 + 64 * SVP + 64 * SQP + 3 * 64) * (int)sizeof(float);
    cudaFuncSetAttribute(attn_tc, cudaFuncAttributeMaxDynamicSharedMemorySize, smem_attn);

    dim3 gemm_grid(EE / 128, MTOT / 128);   // (8, 32)
    gemm_tc<<<gemm_grid, 256>>>(q, Wq, bq, Qh, MTOT, EE, EE);
    gemm_tc<<<gemm_grid, 256>>>(k, Wk, bk, Kh, MTOT, EE, EE);
    gemm_tc<<<gemm_grid, 256>>>(v, Wv, bv, Vh, MTOT, EE, EE);

    dim3 attn_grid(SS / 64, HH, BB);        // (32, 16, 2)
    attn_tc<<<attn_grid, 256, smem_attn>>>(Qh, Kh, Vh, Ctx);

    gemm_tc<<<gemm_grid, 256>>>(Ctx, Wo, bo, out, MTOT, EE, EE);
}

// round 9
// speedup vs baseline: 3.5548x; 1.4434x over previous
#include <cuda_runtime.h>
#include <cuda_fp16.h>
#include <math.h>
#include <stdint.h>

#define BB 2
#define SS 2048
#define EE 1024
#define HH 16
#define DD 64
#define MTOT (BB * SS)   // 4096

__device__ float g_Qh[MTOT * EE];
__device__ float g_Kh[MTOT * EE];
__device__ float g_Vh[MTOT * EE];
__device__ float g_Ctx[MTOT * EE];

// ---------------------------------------------------------------------------
// helpers
// ---------------------------------------------------------------------------
__device__ __forceinline__ uint32_t f2tf(float f) {
    uint32_t u;
    asm("cvt.rna.tf32.f32 %0, %1;" : "=r"(u) : "f"(f));
    return u;
}

__device__ __forceinline__ void mma8(float* c, const uint32_t* a, const uint32_t* b) {
    asm volatile(
        "mma.sync.aligned.m16n8k8.row.col.f32.tf32.tf32.f32 "
        "{%0,%1,%2,%3},{%4,%5,%6,%7},{%8,%9},{%0,%1,%2,%3};"
        : "+f"(c[0]), "+f"(c[1]), "+f"(c[2]), "+f"(c[3])
        : "r"(a[0]), "r"(a[1]), "r"(a[2]), "r"(a[3]), "r"(b[0]), "r"(b[1]));
}

__device__ __forceinline__ void mma16h(float* c, const uint32_t* a, const uint32_t* b) {
    asm volatile(
        "mma.sync.aligned.m16n8k16.row.col.f32.f16.f16.f32 "
        "{%0,%1,%2,%3},{%4,%5,%6,%7},{%8,%9},{%0,%1,%2,%3};"
        : "+f"(c[0]), "+f"(c[1]), "+f"(c[2]), "+f"(c[3])
        : "r"(a[0]), "r"(a[1]), "r"(a[2]), "r"(a[3]), "r"(b[0]), "r"(b[1]));
}

__device__ __forceinline__ uint32_t h2pack(float lo, float hi) {
    __half2 h = __floats2half2_rn(lo, hi);
    return *reinterpret_cast<uint32_t*>(&h);
}

// ---------------------------------------------------------------------------
// GEMM: C[M,N] = A[M,K] @ W[N,K]^T + bias[N]   (tf32 tensor-core)
// Block tile 128x128, BK=32, 256 threads (8 warps, 4x2 warp grid, 32x64/warp)
// ---------------------------------------------------------------------------
#define GKP 36   // stride for 32-wide tf32 tiles (fragment bank = 4g+tig, conflict-free)

__global__ __launch_bounds__(256, 2) void gemm_tc(
    const float* __restrict__ A, const float* __restrict__ W,
    const float* __restrict__ bias, float* __restrict__ C,
    int M, int N, int K)
{
    __shared__ uint32_t sA[128 * GKP];
    __shared__ uint32_t sW[128 * GKP];

    const int tid = threadIdx.x;
    const int lane = tid & 31, warp = tid >> 5;
    const int wm = warp >> 1;
    const int wn = warp & 1;
    const int g = lane >> 2, tig = lane & 3;

    const int row0 = blockIdx.y * 128;
    const int col0 = blockIdx.x * 128;

    float acc[2][8][4];
#pragma unroll
    for (int i = 0; i < 2; i++)
#pragma unroll
        for (int j = 0; j < 8; j++)
#pragma unroll
            for (int l = 0; l < 4; l++) acc[i][j][l] = 0.0f;

    for (int k0 = 0; k0 < K; k0 += 32) {
#pragma unroll
        for (int p = 0; p < 4; p++) {
            int i = tid + p * 256;
            int r = i >> 3;
            int c = (i & 7) << 2;
            float4 va = *(const float4*)&A[(size_t)(row0 + r) * K + k0 + c];
            sA[r * GKP + c + 0] = f2tf(va.x);
            sA[r * GKP + c + 1] = f2tf(va.y);
            sA[r * GKP + c + 2] = f2tf(va.z);
            sA[r * GKP + c + 3] = f2tf(va.w);
            float4 vw = *(const float4*)&W[(size_t)(col0 + r) * K + k0 + c];
            sW[r * GKP + c + 0] = f2tf(vw.x);
            sW[r * GKP + c + 1] = f2tf(vw.y);
            sW[r * GKP + c + 2] = f2tf(vw.z);
            sW[r * GKP + c + 3] = f2tf(vw.w);
        }
        __syncthreads();

#pragma unroll
        for (int ks = 0; ks < 4; ks++) {
            uint32_t af[2][4], bf[8][2];
#pragma unroll
            for (int mt = 0; mt < 2; mt++) {
                int rb = wm * 32 + mt * 16;
                af[mt][0] = sA[(rb + g) * GKP + ks * 8 + tig];
                af[mt][1] = sA[(rb + 8 + g) * GKP + ks * 8 + tig];
                af[mt][2] = sA[(rb + g) * GKP + ks * 8 + tig + 4];
                af[mt][3] = sA[(rb + 8 + g) * GKP + ks * 8 + tig + 4];
            }
#pragma unroll
            for (int nt = 0; nt < 8; nt++) {
                int cb = wn * 64 + nt * 8;
                bf[nt][0] = sW[(cb + g) * GKP + ks * 8 + tig];
                bf[nt][1] = sW[(cb + g) * GKP + ks * 8 + tig + 4];
            }
#pragma unroll
            for (int mt = 0; mt < 2; mt++)
#pragma unroll
                for (int nt = 0; nt < 8; nt++)
                    mma8(acc[mt][nt], af[mt], bf[nt]);
        }
        __syncthreads();
    }

#pragma unroll
    for (int mt = 0; mt < 2; mt++) {
        int r = row0 + wm * 32 + mt * 16;
#pragma unroll
        for (int nt = 0; nt < 8; nt++) {
            int c = col0 + wn * 64 + nt * 8 + 2 * tig;
            float b0 = bias[c], b1 = bias[c + 1];
            C[(size_t)(r + g) * N + c]         = acc[mt][nt][0] + b0;
            C[(size_t)(r + g) * N + c + 1]     = acc[mt][nt][1] + b1;
            C[(size_t)(r + 8 + g) * N + c]     = acc[mt][nt][2] + b0;
            C[(size_t)(r + 8 + g) * N + c + 1] = acc[mt][nt][3] + b1;
        }
    }
}

// ---------------------------------------------------------------------------
// Flash attention v2 style: block = (b, h, 128-row Q tile), 8 warps.
// Each warp: 16 q-rows x 64 keys x 64 d. S/P/softmax entirely in registers.
// QK^T in tf32, PV in fp16 (P in [0,1]; fp16 mantissa == tf32 mantissa).
// ---------------------------------------------------------------------------
#define SKP 68   // stride for 64-word-wide tf32 tiles (sK / staged Q) — MUST be >= 64
#define SVP 36   // stride for 32-word-wide half2 V^T tile [d][keypair]

// 0.25 * log2(e): softmax computed in exp2 domain with folded 1/sqrt(H) scale
#define SCL2E 0.3606737602222409f

__global__ __launch_bounds__(256) void attn_tc2(
    const float* __restrict__ Qh, const float* __restrict__ Kh,
    const float* __restrict__ Vh, float* __restrict__ Ctx)
{
    __shared__ uint32_t sK[64 * SKP];    // tf32 K tile [key][d] (also Q staging)
    __shared__ uint32_t sVt[64 * SVP];   // half2 V^T tile [d][keypair]

    const int tid = threadIdx.x;
    const int lane = tid & 31, warp = tid >> 5;
    const int g = lane >> 2, tig = lane & 3;

    const int b = blockIdx.z, h = blockIdx.y, q0 = blockIdx.x * 128;
    const int hd = h * DD;

    // ---- Stage Q through sK (two 64-row halves), fragments to registers ----
    uint32_t qa[8][4];
#pragma unroll
    for (int hf = 0; hf < 2; hf++) {
#pragma unroll
        for (int p = 0; p < 4; p++) {
            int i = tid + p * 256;
            int r = i >> 4, c = (i & 15) << 2;
            float4 v = *(const float4*)&Qh[(size_t)(b * SS + q0 + hf * 64 + r) * EE + hd + c];
            sK[r * SKP + c + 0] = f2tf(v.x);
            sK[r * SKP + c + 1] = f2tf(v.y);
            sK[r * SKP + c + 2] = f2tf(v.z);
            sK[r * SKP + c + 3] = f2tf(v.w);
        }
        __syncthreads();
        if ((warp >> 2) == hf) {
            int rw = (warp & 3) * 16;
#pragma unroll
            for (int ks = 0; ks < 8; ks++) {
                qa[ks][0] = sK[(rw + g) * SKP + ks * 8 + tig];
                qa[ks][1] = sK[(rw + 8 + g) * SKP + ks * 8 + tig];
                qa[ks][2] = sK[(rw + g) * SKP + ks * 8 + tig + 4];
                qa[ks][3] = sK[(rw + 8 + g) * SKP + ks * 8 + tig + 4];
            }
        }
        __syncthreads();
    }

    float m0 = -INFINITY, m1 = -INFINITY, l0 = 0.0f, l1 = 0.0f;
    float o[8][4];
#pragma unroll
    for (int nt = 0; nt < 8; nt++)
#pragma unroll
        for (int l = 0; l < 4; l++) o[nt][l] = 0.0f;

    for (int kv0 = 0; kv0 < SS; kv0 += 64) {
        // ---- Load K tile (tf32, coalesced) ----
#pragma unroll
        for (int p = 0; p < 4; p++) {
            int i = tid + p * 256;
            int r = i >> 4, c = (i & 15) << 2;
            float4 vk = *(const float4*)&Kh[(size_t)(b * SS + kv0 + r) * EE + hd + c];
            sK[r * SKP + c + 0] = f2tf(vk.x);
            sK[r * SKP + c + 1] = f2tf(vk.y);
            sK[r * SKP + c + 2] = f2tf(vk.z);
            sK[r * SKP + c + 3] = f2tf(vk.w);
        }
        // ---- Load V tile transposed as half2 key-pairs (conflict-free STS) ----
#pragma unroll
        for (int it = 0; it < 2; it++) {
            int i = tid + it * 256;
            int pair = i & 31;           // key pair 0..31
            int c4 = i >> 5;             // d quad 0..15
            int d = c4 * 4;
            const float* vp = &Vh[(size_t)(b * SS + kv0 + 2 * pair) * EE + hd + d];
            float4 v0 = *(const float4*)vp;
            float4 v1 = *(const float4*)(vp + EE);
            sVt[(d + 0) * SVP + pair] = h2pack(v0.x, v1.x);
            sVt[(d + 1) * SVP + pair] = h2pack(v0.y, v1.y);
            sVt[(d + 2) * SVP + pair] = h2pack(v0.z, v1.z);
            sVt[(d + 3) * SVP + pair] = h2pack(v0.w, v1.w);
        }
        __syncthreads();

        // ---- S = Q K^T (registers) ----
        float sc[8][4];
#pragma unroll
        for (int nt = 0; nt < 8; nt++)
#pragma unroll
            for (int l = 0; l < 4; l++) sc[nt][l] = 0.0f;

#pragma unroll
        for (int ks = 0; ks < 8; ks++) {
#pragma unroll
            for (int nt = 0; nt < 8; nt++) {
                uint32_t bf[2];
                bf[0] = sK[(nt * 8 + g) * SKP + ks * 8 + tig];
                bf[1] = sK[(nt * 8 + g) * SKP + ks * 8 + tig + 4];
                mma8(sc[nt], qa[ks], bf);
            }
        }

        // ---- Online softmax in registers (rows g and g+8 of warp tile) ----
        float mx0 = -INFINITY, mx1 = -INFINITY;
#pragma unroll
        for (int nt = 0; nt < 8; nt++) {
            mx0 = fmaxf(mx0, fmaxf(sc[nt][0], sc[nt][1]));
            mx1 = fmaxf(mx1, fmaxf(sc[nt][2], sc[nt][3]));
        }
        mx0 = fmaxf(mx0, __shfl_xor_sync(0xFFFFFFFFu, mx0, 1));
        mx0 = fmaxf(mx0, __shfl_xor_sync(0xFFFFFFFFu, mx0, 2));
        mx1 = fmaxf(mx1, __shfl_xor_sync(0xFFFFFFFFu, mx1, 1));
        mx1 = fmaxf(mx1, __shfl_xor_sync(0xFFFFFFFFu, mx1, 2));

        float mn0 = fmaxf(m0, mx0 * SCL2E);
        float mn1 = fmaxf(m1, mx1 * SCL2E);
        float al0 = exp2f(m0 - mn0);
        float al1 = exp2f(m1 - mn1);
        m0 = mn0; m1 = mn1;

        float s0 = 0.0f, s1 = 0.0f;
#pragma unroll
        for (int nt = 0; nt < 8; nt++) {
            sc[nt][0] = exp2f(sc[nt][0] * SCL2E - mn0);
            sc[nt][1] = exp2f(sc[nt][1] * SCL2E - mn0);
            sc[nt][2] = exp2f(sc[nt][2] * SCL2E - mn1);
            sc[nt][3] = exp2f(sc[nt][3] * SCL2E - mn1);
            s0 += sc[nt][0] + sc[nt][1];
            s1 += sc[nt][2] + sc[nt][3];
        }
        s0 += __shfl_xor_sync(0xFFFFFFFFu, s0, 1);
        s0 += __shfl_xor_sync(0xFFFFFFFFu, s0, 2);
        s1 += __shfl_xor_sync(0xFFFFFFFFu, s1, 1);
        s1 += __shfl_xor_sync(0xFFFFFFFFu, s1, 2);
        l0 = l0 * al0 + s0;
        l1 = l1 * al1 + s1;

#pragma unroll
        for (int nt = 0; nt < 8; nt++) {
            o[nt][0] *= al0; o[nt][1] *= al0;
            o[nt][2] *= al1; o[nt][3] *= al1;
        }

        // ---- O += P @ V (fp16 MMA; P already in A-fragment layout) ----
#pragma unroll
        for (int kc = 0; kc < 4; kc++) {
            uint32_t pa[4];
            pa[0] = h2pack(sc[2 * kc][0], sc[2 * kc][1]);
            pa[1] = h2pack(sc[2 * kc][2], sc[2 * kc][3]);
            pa[2] = h2pack(sc[2 * kc + 1][0], sc[2 * kc + 1][1]);
            pa[3] = h2pack(sc[2 * kc + 1][2], sc[2 * kc + 1][3]);
#pragma unroll
            for (int nt = 0; nt < 8; nt++) {
                uint32_t bf[2];
                bf[0] = sVt[(nt * 8 + g) * SVP + kc * 8 + tig];
                bf[1] = sVt[(nt * 8 + g) * SVP + kc * 8 + tig + 4];
                mma16h(o[nt], pa, bf);
            }
        }
        __syncthreads();
    }

    // ---- Epilogue ----
    const float i0 = 1.0f / l0;
    const float i1 = 1.0f / l1;
    const size_t rA = (size_t)(b * SS + q0 + warp * 16 + g) * EE + hd;
    const size_t rB = rA + 8 * EE;
#pragma unroll
    for (int nt = 0; nt < 8; nt++) {
        int d = nt * 8 + 2 * tig;
        Ctx[rA + d]     = o[nt][0] * i0;
        Ctx[rA + d + 1] = o[nt][1] * i0;
        Ctx[rB + d]     = o[nt][2] * i1;
        Ctx[rB + d + 1] = o[nt][3] * i1;
    }
}

// ---------------------------------------------------------------------------
// Launch
// ---------------------------------------------------------------------------
extern "C" void kernel_launch(void* const* d_in, const int* in_sizes, int n_in,
                              void* d_out, int out_size)
{
    const float* q  = (const float*)d_in[0];
    const float* k  = (const float*)d_in[1];
    const float* v  = (const float*)d_in[2];
    const float* Wq = (const float*)d_in[3];
    const float* bq = (const float*)d_in[4];
    const float* Wk = (const float*)d_in[5];
    const float* bk = (const float*)d_in[6];
    const float* Wv = (const float*)d_in[7];
    const float* bv = (const float*)d_in[8];
    const float* Wo = (const float*)d_in[9];
    const float* bo = (const float*)d_in[10];
    float* out = (float*)d_out;

    float* Qh;  cudaGetSymbolAddress((void**)&Qh,  g_Qh);
    float* Kh;  cudaGetSymbolAddress((void**)&Kh,  g_Kh);
    float* Vh;  cudaGetSymbolAddress((void**)&Vh,  g_Vh);
    float* Ctx; cudaGetSymbolAddress((void**)&Ctx, g_Ctx);

    dim3 gemm_grid(EE / 128, MTOT / 128);   // (8, 32)
    gemm_tc<<<gemm_grid, 256>>>(q, Wq, bq, Qh, MTOT, EE, EE);
    gemm_tc<<<gemm_grid, 256>>>(k, Wk, bk, Kh, MTOT, EE, EE);
    gemm_tc<<<gemm_grid, 256>>>(v, Wv, bv, Vh, MTOT, EE, EE);

    dim3 attn_grid(SS / 128, HH, BB);       // (16, 16, 2)
    attn_tc2<<<attn_grid, 256>>>(Qh, Kh, Vh, Ctx);

    gemm_tc<<<gemm_grid, 256>>>(Ctx, Wo, bo, out, MTOT, EE, EE);
}

// round 10
// speedup vs baseline: 4.2008x; 1.1817x over previous
#include <cuda_runtime.h>
#include <cuda_fp16.h>
#include <math.h>
#include <stdint.h>

#define BB 2
#define SS 2048
#define EE 1024
#define HH 16
#define DD 64
#define MTOT (BB * SS)   // 4096

__device__ float g_Qh[MTOT * EE];
__device__ float g_Kh[MTOT * EE];
__device__ float g_Vh[MTOT * EE];
__device__ float g_Ctx[MTOT * EE];

// ---------------------------------------------------------------------------
// helpers
// ---------------------------------------------------------------------------
__device__ __forceinline__ uint32_t f2tf(float f) {
    uint32_t u;
    asm("cvt.rna.tf32.f32 %0, %1;" : "=r"(u) : "f"(f));
    return u;
}

__device__ __forceinline__ void mma8(float* c, const uint32_t* a, const uint32_t* b) {
    asm volatile(
        "mma.sync.aligned.m16n8k8.row.col.f32.tf32.tf32.f32 "
        "{%0,%1,%2,%3},{%4,%5,%6,%7},{%8,%9},{%0,%1,%2,%3};"
        : "+f"(c[0]), "+f"(c[1]), "+f"(c[2]), "+f"(c[3])
        : "r"(a[0]), "r"(a[1]), "r"(a[2]), "r"(a[3]), "r"(b[0]), "r"(b[1]));
}

__device__ __forceinline__ void mma16h(float* c, const uint32_t* a, const uint32_t* b) {
    asm volatile(
        "mma.sync.aligned.m16n8k16.row.col.f32.f16.f16.f32 "
        "{%0,%1,%2,%3},{%4,%5,%6,%7},{%8,%9},{%0,%1,%2,%3};"
        : "+f"(c[0]), "+f"(c[1]), "+f"(c[2]), "+f"(c[3])
        : "r"(a[0]), "r"(a[1]), "r"(a[2]), "r"(a[3]), "r"(b[0]), "r"(b[1]));
}

__device__ __forceinline__ uint32_t h2pack(float lo, float hi) {
    __half2 h = __floats2half2_rn(lo, hi);
    return *reinterpret_cast<uint32_t*>(&h);
}

// ---------------------------------------------------------------------------
// GEMM: C[M,N] = A[M,K] @ W[N,K]^T + bias[N]   (tf32 tensor-core)
// ---------------------------------------------------------------------------
#define GKP 36

__global__ __launch_bounds__(256, 2) void gemm_tc(
    const float* __restrict__ A, const float* __restrict__ W,
    const float* __restrict__ bias, float* __restrict__ C,
    int M, int N, int K)
{
    __shared__ uint32_t sA[128 * GKP];
    __shared__ uint32_t sW[128 * GKP];

    const int tid = threadIdx.x;
    const int lane = tid & 31, warp = tid >> 5;
    const int wm = warp >> 1;
    const int wn = warp & 1;
    const int g = lane >> 2, tig = lane & 3;

    const int row0 = blockIdx.y * 128;
    const int col0 = blockIdx.x * 128;

    float acc[2][8][4];
#pragma unroll
    for (int i = 0; i < 2; i++)
#pragma unroll
        for (int j = 0; j < 8; j++)
#pragma unroll
            for (int l = 0; l < 4; l++) acc[i][j][l] = 0.0f;

    for (int k0 = 0; k0 < K; k0 += 32) {
#pragma unroll
        for (int p = 0; p < 4; p++) {
            int i = tid + p * 256;
            int r = i >> 3;
            int c = (i & 7) << 2;
            float4 va = *(const float4*)&A[(size_t)(row0 + r) * K + k0 + c];
            sA[r * GKP + c + 0] = f2tf(va.x);
            sA[r * GKP + c + 1] = f2tf(va.y);
            sA[r * GKP + c + 2] = f2tf(va.z);
            sA[r * GKP + c + 3] = f2tf(va.w);
            float4 vw = *(const float4*)&W[(size_t)(col0 + r) * K + k0 + c];
            sW[r * GKP + c + 0] = f2tf(vw.x);
            sW[r * GKP + c + 1] = f2tf(vw.y);
            sW[r * GKP + c + 2] = f2tf(vw.z);
            sW[r * GKP + c + 3] = f2tf(vw.w);
        }
        __syncthreads();

#pragma unroll
        for (int ks = 0; ks < 4; ks++) {
            uint32_t af[2][4], bf[8][2];
#pragma unroll
            for (int mt = 0; mt < 2; mt++) {
                int rb = wm * 32 + mt * 16;
                af[mt][0] = sA[(rb + g) * GKP + ks * 8 + tig];
                af[mt][1] = sA[(rb + 8 + g) * GKP + ks * 8 + tig];
                af[mt][2] = sA[(rb + g) * GKP + ks * 8 + tig + 4];
                af[mt][3] = sA[(rb + 8 + g) * GKP + ks * 8 + tig + 4];
            }
#pragma unroll
            for (int nt = 0; nt < 8; nt++) {
                int cb = wn * 64 + nt * 8;
                bf[nt][0] = sW[(cb + g) * GKP + ks * 8 + tig];
                bf[nt][1] = sW[(cb + g) * GKP + ks * 8 + tig + 4];
            }
#pragma unroll
            for (int mt = 0; mt < 2; mt++)
#pragma unroll
                for (int nt = 0; nt < 8; nt++)
                    mma8(acc[mt][nt], af[mt], bf[nt]);
        }
        __syncthreads();
    }

#pragma unroll
    for (int mt = 0; mt < 2; mt++) {
        int r = row0 + wm * 32 + mt * 16;
#pragma unroll
        for (int nt = 0; nt < 8; nt++) {
            int c = col0 + wn * 64 + nt * 8 + 2 * tig;
            float b0 = bias[c], b1 = bias[c + 1];
            C[(size_t)(r + g) * N + c]         = acc[mt][nt][0] + b0;
            C[(size_t)(r + g) * N + c + 1]     = acc[mt][nt][1] + b1;
            C[(size_t)(r + 8 + g) * N + c]     = acc[mt][nt][2] + b0;
            C[(size_t)(r + 8 + g) * N + c + 1] = acc[mt][nt][3] + b1;
        }
    }
}

// ---------------------------------------------------------------------------
// Flash attention, all-fp16 MMA, double-buffered K/V, 1 barrier per kv tile.
// Block = (b, h, 128-row Q tile), 8 warps; warp = 16 q-rows x 64 keys x 64 d.
// ---------------------------------------------------------------------------
#define HKP 36   // stride (words) for all 32-half2-wide tiles

#define SCL2E 0.3606737602222409f   // 0.25 * log2(e)

__global__ __launch_bounds__(256, 2) void attn_tc3(
    const float* __restrict__ Qh, const float* __restrict__ Kh,
    const float* __restrict__ Vh, float* __restrict__ Ctx)
{
    __shared__ uint32_t sKh[2][64 * HKP];   // half2 K tile [key][dpair]
    __shared__ uint32_t sVb[2][64 * HKP];   // half2 V^T tile [d][keypair]

    const int tid = threadIdx.x;
    const int lane = tid & 31, warp = tid >> 5;
    const int g = lane >> 2, tig = lane & 3;

    const int b = blockIdx.z, h = blockIdx.y, q0 = blockIdx.x * 128;
    const int hd = h * DD;

    // ---- Stage Q (two 64-row halves into sKh[0], sKh[1]), frags to regs ----
#pragma unroll
    for (int hf = 0; hf < 2; hf++) {
#pragma unroll
        for (int p = 0; p < 4; p++) {
            int i = tid + p * 256;
            int r = i >> 4, c4 = i & 15;
            float4 v = *(const float4*)&Qh[(size_t)(b * SS + q0 + hf * 64 + r) * EE + hd + 4 * c4];
            sKh[hf][r * HKP + 2 * c4]     = h2pack(v.x, v.y);
            sKh[hf][r * HKP + 2 * c4 + 1] = h2pack(v.z, v.w);
        }
    }
    __syncthreads();

    uint32_t qa[4][4];
    {
        const uint32_t* sQ = sKh[warp >> 2];
        int rw = (warp & 3) * 16;
#pragma unroll
        for (int kc = 0; kc < 4; kc++) {
            qa[kc][0] = sQ[(rw + g) * HKP + kc * 8 + tig];
            qa[kc][1] = sQ[(rw + 8 + g) * HKP + kc * 8 + tig];
            qa[kc][2] = sQ[(rw + g) * HKP + kc * 8 + tig + 4];
            qa[kc][3] = sQ[(rw + 8 + g) * HKP + kc * 8 + tig + 4];
        }
    }
    __syncthreads();

    float m0 = -INFINITY, m1 = -INFINITY, l0 = 0.0f, l1 = 0.0f;
    float o[8][4];
#pragma unroll
    for (int nt = 0; nt < 8; nt++)
#pragma unroll
        for (int l = 0; l < 4; l++) o[nt][l] = 0.0f;

    // precomputed per-thread load offsets
    const int kr = tid >> 4;              // K row (per p: +16)
    const int kc4 = tid & 15;             // K d-quad
    const int vpair = tid & 31;           // V key pair (per it: row pair)
    const int vd = (tid >> 5) * 4;        // V d base (per it: +32)

    uint32_t kst[8], vst[8];

    // ---- prologue: stage tile 0 ----
    {
#pragma unroll
        for (int p = 0; p < 4; p++) {
            float4 vk = *(const float4*)&Kh[(size_t)(b * SS + kr + p * 16) * EE + hd + 4 * kc4];
            kst[2 * p] = h2pack(vk.x, vk.y);
            kst[2 * p + 1] = h2pack(vk.z, vk.w);
        }
#pragma unroll
        for (int it = 0; it < 2; it++) {
            const float* vp = &Vh[(size_t)(b * SS + 2 * vpair) * EE + hd + vd + it * 32];
            float4 v0 = *(const float4*)vp;
            float4 v1 = *(const float4*)(vp + EE);
            vst[4 * it + 0] = h2pack(v0.x, v1.x);
            vst[4 * it + 1] = h2pack(v0.y, v1.y);
            vst[4 * it + 2] = h2pack(v0.z, v1.z);
            vst[4 * it + 3] = h2pack(v0.w, v1.w);
        }
#pragma unroll
        for (int p = 0; p < 4; p++) {
            sKh[0][(kr + p * 16) * HKP + 2 * kc4]     = kst[2 * p];
            sKh[0][(kr + p * 16) * HKP + 2 * kc4 + 1] = kst[2 * p + 1];
        }
#pragma unroll
        for (int it = 0; it < 2; it++)
#pragma unroll
            for (int j = 0; j < 4; j++)
                sVb[0][(vd + it * 32 + j) * HKP + vpair] = vst[4 * it + j];
        __syncthreads();
    }

    for (int t = 0; t < SS / 64; t++) {
        const int bf = t & 1;
        const int kvn = (t + 1) * 64;

        // ---- issue LDG for tile t+1 early ----
        if (kvn < SS) {
#pragma unroll
            for (int p = 0; p < 4; p++) {
                float4 vk = *(const float4*)&Kh[(size_t)(b * SS + kvn + kr + p * 16) * EE + hd + 4 * kc4];
                kst[2 * p] = h2pack(vk.x, vk.y);
                kst[2 * p + 1] = h2pack(vk.z, vk.w);
            }
#pragma unroll
            for (int it = 0; it < 2; it++) {
                const float* vp = &Vh[(size_t)(b * SS + kvn + 2 * vpair) * EE + hd + vd + it * 32];
                float4 v0 = *(const float4*)vp;
                float4 v1 = *(const float4*)(vp + EE);
                vst[4 * it + 0] = h2pack(v0.x, v1.x);
                vst[4 * it + 1] = h2pack(v0.y, v1.y);
                vst[4 * it + 2] = h2pack(v0.z, v1.z);
                vst[4 * it + 3] = h2pack(v0.w, v1.w);
            }
        }

        // ---- S = Q K^T (fp16 MMA) ----
        const uint32_t* sK = sKh[bf];
        const uint32_t* sV = sVb[bf];

        float sc[8][4];
#pragma unroll
        for (int nt = 0; nt < 8; nt++)
#pragma unroll
            for (int l = 0; l < 4; l++) sc[nt][l] = 0.0f;

#pragma unroll
        for (int kc = 0; kc < 4; kc++) {
#pragma unroll
            for (int nt = 0; nt < 8; nt++) {
                uint32_t bb[2];
                bb[0] = sK[(nt * 8 + g) * HKP + kc * 8 + tig];
                bb[1] = sK[(nt * 8 + g) * HKP + kc * 8 + tig + 4];
                mma16h(sc[nt], qa[kc], bb);
            }
        }

        // ---- online softmax in registers ----
        float mx0 = -INFINITY, mx1 = -INFINITY;
#pragma unroll
        for (int nt = 0; nt < 8; nt++) {
            mx0 = fmaxf(mx0, fmaxf(sc[nt][0], sc[nt][1]));
            mx1 = fmaxf(mx1, fmaxf(sc[nt][2], sc[nt][3]));
        }
        mx0 = fmaxf(mx0, __shfl_xor_sync(0xFFFFFFFFu, mx0, 1));
        mx0 = fmaxf(mx0, __shfl_xor_sync(0xFFFFFFFFu, mx0, 2));
        mx1 = fmaxf(mx1, __shfl_xor_sync(0xFFFFFFFFu, mx1, 1));
        mx1 = fmaxf(mx1, __shfl_xor_sync(0xFFFFFFFFu, mx1, 2));

        float mn0 = fmaxf(m0, mx0 * SCL2E);
        float mn1 = fmaxf(m1, mx1 * SCL2E);
        float al0 = exp2f(m0 - mn0);
        float al1 = exp2f(m1 - mn1);
        m0 = mn0; m1 = mn1;

        float s0 = 0.0f, s1 = 0.0f;
#pragma unroll
        for (int nt = 0; nt < 8; nt++) {
            sc[nt][0] = exp2f(sc[nt][0] * SCL2E - mn0);
            sc[nt][1] = exp2f(sc[nt][1] * SCL2E - mn0);
            sc[nt][2] = exp2f(sc[nt][2] * SCL2E - mn1);
            sc[nt][3] = exp2f(sc[nt][3] * SCL2E - mn1);
            s0 += sc[nt][0] + sc[nt][1];
            s1 += sc[nt][2] + sc[nt][3];
        }
        s0 += __shfl_xor_sync(0xFFFFFFFFu, s0, 1);
        s0 += __shfl_xor_sync(0xFFFFFFFFu, s0, 2);
        s1 += __shfl_xor_sync(0xFFFFFFFFu, s1, 1);
        s1 += __shfl_xor_sync(0xFFFFFFFFu, s1, 2);
        l0 = l0 * al0 + s0;
        l1 = l1 * al1 + s1;

#pragma unroll
        for (int nt = 0; nt < 8; nt++) {
            o[nt][0] *= al0; o[nt][1] *= al0;
            o[nt][2] *= al1; o[nt][3] *= al1;
        }

        // ---- O += P @ V ----
#pragma unroll
        for (int kc = 0; kc < 4; kc++) {
            uint32_t pa[4];
            pa[0] = h2pack(sc[2 * kc][0], sc[2 * kc][1]);
            pa[1] = h2pack(sc[2 * kc][2], sc[2 * kc][3]);
            pa[2] = h2pack(sc[2 * kc + 1][0], sc[2 * kc + 1][1]);
            pa[3] = h2pack(sc[2 * kc + 1][2], sc[2 * kc + 1][3]);
#pragma unroll
            for (int nt = 0; nt < 8; nt++) {
                uint32_t bb[2];
                bb[0] = sV[(nt * 8 + g) * HKP + kc * 8 + tig];
                bb[1] = sV[(nt * 8 + g) * HKP + kc * 8 + tig + 4];
                mma16h(o[nt], pa, bb);
            }
        }

        // ---- store staged tile t+1 into the other buffer ----
        if (kvn < SS) {
            const int nb = bf ^ 1;
#pragma unroll
            for (int p = 0; p < 4; p++) {
                sKh[nb][(kr + p * 16) * HKP + 2 * kc4]     = kst[2 * p];
                sKh[nb][(kr + p * 16) * HKP + 2 * kc4 + 1] = kst[2 * p + 1];
            }
#pragma unroll
            for (int it = 0; it < 2; it++)
#pragma unroll
                for (int j = 0; j < 4; j++)
                    sVb[nb][(vd + it * 32 + j) * HKP + vpair] = vst[4 * it + j];
        }
        __syncthreads();
    }

    // ---- Epilogue ----
    const float i0 = 1.0f / l0;
    const float i1 = 1.0f / l1;
    const size_t rA = (size_t)(b * SS + q0 + warp * 16 + g) * EE + hd;
    const size_t rB = rA + 8 * EE;
#pragma unroll
    for (int nt = 0; nt < 8; nt++) {
        int d = nt * 8 + 2 * tig;
        Ctx[rA + d]     = o[nt][0] * i0;
        Ctx[rA + d + 1] = o[nt][1] * i0;
        Ctx[rB + d]     = o[nt][2] * i1;
        Ctx[rB + d + 1] = o[nt][3] * i1;
    }
}

// ---------------------------------------------------------------------------
// Launch
// ---------------------------------------------------------------------------
extern "C" void kernel_launch(void* const* d_in, const int* in_sizes, int n_in,
                              void* d_out, int out_size)
{
    const float* q  = (const float*)d_in[0];
    const float* k  = (const float*)d_in[1];
    const float* v  = (const float*)d_in[2];
    const float* Wq = (const float*)d_in[3];
    const float* bq = (const float*)d_in[4];
    const float* Wk = (const float*)d_in[5];
    const float* bk = (const float*)d_in[6];
    const float* Wv = (const float*)d_in[7];
    const float* bv = (const float*)d_in[8];
    const float* Wo = (const float*)d_in[9];
    const float* bo = (const float*)d_in[10];
    float* out = (float*)d_out;

    float* Qh;  cudaGetSymbolAddress((void**)&Qh,  g_Qh);
    float* Kh;  cudaGetSymbolAddress((void**)&Kh,  g_Kh);
    float* Vh;  cudaGetSymbolAddress((void**)&Vh,  g_Vh);
    float* Ctx; cudaGetSymbolAddress((void**)&Ctx, g_Ctx);

    dim3 gemm_grid(EE / 128, MTOT / 128);   // (8, 32)
    gemm_tc<<<gemm_grid, 256>>>(q, Wq, bq, Qh, MTOT, EE, EE);
    gemm_tc<<<gemm_grid, 256>>>(k, Wk, bk, Kh, MTOT, EE, EE);
    gemm_tc<<<gemm_grid, 256>>>(v, Wv, bv, Vh, MTOT, EE, EE);

    dim3 attn_grid(SS / 128, HH, BB);       // (16, 16, 2)
    attn_tc3<<<attn_grid, 256>>>(Qh, Kh, Vh, Ctx);

    gemm_tc<<<gemm_grid, 256>>>(Ctx, Wo, bo, out, MTOT, EE, EE);
}

// round 14
// speedup vs baseline: 5.9386x; 1.4137x over previous
#include <cuda_runtime.h>
#include <cuda_fp16.h>
#include <math.h>
#include <stdint.h>

#define BB 2
#define SS 2048
#define EE 1024
#define HH 16
#define DD 64
#define MTOT (BB * SS)   // 4096

// Scratch in half precision
__device__ __half g_Qh[MTOT * EE];
__device__ __half g_Kh[MTOT * EE];
__device__ __half g_Vh[MTOT * EE];
__device__ __half g_Ctx[MTOT * EE];

// ---------------------------------------------------------------------------
// helpers
// ---------------------------------------------------------------------------
__device__ __forceinline__ void mma16h(float* c, const uint32_t* a, const uint32_t* b) {
    asm volatile(
        "mma.sync.aligned.m16n8k16.row.col.f32.f16.f16.f32 "
        "{%0,%1,%2,%3},{%4,%5,%6,%7},{%8,%9},{%0,%1,%2,%3};"
        : "+f"(c[0]), "+f"(c[1]), "+f"(c[2]), "+f"(c[3])
        : "r"(a[0]), "r"(a[1]), "r"(a[2]), "r"(a[3]), "r"(b[0]), "r"(b[1]));
}

__device__ __forceinline__ uint32_t h2pack(float lo, float hi) {
    __half2 h = __floats2half2_rn(lo, hi);
    return *reinterpret_cast<uint32_t*>(&h);
}

// half2(a.lo, b.lo) and half2(a.hi, b.hi) from two packed half2 words
__device__ __forceinline__ uint32_t lows2(uint32_t a, uint32_t b) {
    uint32_t r; asm("prmt.b32 %0, %1, %2, 0x5410;" : "=r"(r) : "r"(a), "r"(b)); return r;
}
__device__ __forceinline__ uint32_t highs2(uint32_t a, uint32_t b) {
    uint32_t r; asm("prmt.b32 %0, %1, %2, 0x7632;" : "=r"(r) : "r"(a), "r"(b)); return r;
}

// ---------------------------------------------------------------------------
// GEMM: C[M,N] = A[M,K] @ W[N,K]^T + bias[N], fp16 MMA, double-buffered.
// Block tile 128x128, BK=32, 256 threads (8 warps, 4x2 grid, 32x64/warp).
// AH: A is __half (else float). CH: C is __half (else float).
// ---------------------------------------------------------------------------
#define GSP 20   // smem stride in half2 words (16 data + 4 pad); bank = (20g+tig)%32 distinct

template<bool AH, bool CH>
__global__ __launch_bounds__(256, 2) void gemm_h(
    const void* __restrict__ Ap, const float* __restrict__ Wp,
    const float* __restrict__ bias, void* __restrict__ Cp)
{
    const int N = EE, K = EE;
    __shared__ uint32_t sA[2][128 * GSP];
    __shared__ uint32_t sW[2][128 * GSP];

    const int tid = threadIdx.x;
    const int lane = tid & 31, warp = tid >> 5;
    const int wm = warp >> 1, wn = warp & 1;
    const int g = lane >> 2, tig = lane & 3;

    const int row0 = blockIdx.y * 128;
    const int col0 = blockIdx.x * 128;

    const float*  Af = (const float*)Ap;
    const __half* Ahp = (const __half*)Ap;

    const int rL = tid >> 3;          // float-path row (per p: +32)
    const int cL = (tid & 7) * 4;     // float-path col (floats)
    const int rH = tid >> 2;          // half-path row (per p: +64)
    const int cH = (tid & 3) * 8;     // half-path col (halfs)

    uint32_t aS[8], wS[8];

    float acc[2][8][4];
#pragma unroll
    for (int i = 0; i < 2; i++)
#pragma unroll
        for (int j = 0; j < 8; j++)
#pragma unroll
            for (int l = 0; l < 4; l++) acc[i][j][l] = 0.0f;

    // ---- stage chunk k0 into registers ----
    auto stage = [&](int k0) {
        if (!AH) {
#pragma unroll
            for (int p = 0; p < 4; p++) {
                float4 v = *(const float4*)&Af[(size_t)(row0 + rL + p * 32) * K + k0 + cL];
                aS[2 * p]     = h2pack(v.x, v.y);
                aS[2 * p + 1] = h2pack(v.z, v.w);
            }
        } else {
#pragma unroll
            for (int p = 0; p < 2; p++) {
                uint4 v = *(const uint4*)&Ahp[(size_t)(row0 + rH + p * 64) * K + k0 + cH];
                aS[4 * p + 0] = v.x; aS[4 * p + 1] = v.y;
                aS[4 * p + 2] = v.z; aS[4 * p + 3] = v.w;
            }
        }
#pragma unroll
        for (int p = 0; p < 4; p++) {
            float4 v = *(const float4*)&Wp[(size_t)(col0 + rL + p * 32) * K + k0 + cL];
            wS[2 * p]     = h2pack(v.x, v.y);
            wS[2 * p + 1] = h2pack(v.z, v.w);
        }
    };
    // ---- commit staged registers into smem buffer ----
    auto commit = [&](int buf) {
        if (!AH) {
#pragma unroll
            for (int p = 0; p < 4; p++) {
                sA[buf][(rL + p * 32) * GSP + (tid & 7) * 2]     = aS[2 * p];
                sA[buf][(rL + p * 32) * GSP + (tid & 7) * 2 + 1] = aS[2 * p + 1];
            }
        } else {
#pragma unroll
            for (int p = 0; p < 2; p++)
#pragma unroll
                for (int j = 0; j < 4; j++)
                    sA[buf][(rH + p * 64) * GSP + (tid & 3) * 4 + j] = aS[4 * p + j];
        }
#pragma unroll
        for (int p = 0; p < 4; p++) {
            sW[buf][(rL + p * 32) * GSP + (tid & 7) * 2]     = wS[2 * p];
            sW[buf][(rL + p * 32) * GSP + (tid & 7) * 2 + 1] = wS[2 * p + 1];
        }
    };

    stage(0);
    commit(0);
    __syncthreads();

    const int NT = K / 32;
    for (int t = 0; t < NT; t++) {
        const int buf = t & 1;
        if (t + 1 < NT) stage((t + 1) * 32);

#pragma unroll
        for (int ks = 0; ks < 2; ks++) {
            uint32_t af[2][4], bf[8][2];
#pragma unroll
            for (int mt = 0; mt < 2; mt++) {
                int rb = wm * 32 + mt * 16;
                af[mt][0] = sA[buf][(rb + g) * GSP + ks * 8 + tig];
                af[mt][1] = sA[buf][(rb + 8 + g) * GSP + ks * 8 + tig];
                af[mt][2] = sA[buf][(rb + g) * GSP + ks * 8 + tig + 4];
                af[mt][3] = sA[buf][(rb + 8 + g) * GSP + ks * 8 + tig + 4];
            }
#pragma unroll
            for (int nt = 0; nt < 8; nt++) {
                int cb = wn * 64 + nt * 8;
                bf[nt][0] = sW[buf][(cb + g) * GSP + ks * 8 + tig];
                bf[nt][1] = sW[buf][(cb + g) * GSP + ks * 8 + tig + 4];
            }
#pragma unroll
            for (int mt = 0; mt < 2; mt++)
#pragma unroll
                for (int nt = 0; nt < 8; nt++)
                    mma16h(acc[mt][nt], af[mt], bf[nt]);
        }

        if (t + 1 < NT) commit(buf ^ 1);
        __syncthreads();
    }

    // ---- epilogue ----
#pragma unroll
    for (int mt = 0; mt < 2; mt++) {
        int r = row0 + wm * 32 + mt * 16;
#pragma unroll
        for (int nt = 0; nt < 8; nt++) {
            int c = col0 + wn * 64 + nt * 8 + 2 * tig;
            float b0 = bias[c], b1 = bias[c + 1];
            if (CH) {
                __half* Ch = (__half*)Cp;
                *(__half2*)&Ch[(size_t)(r + g) * N + c] =
                    __floats2half2_rn(acc[mt][nt][0] + b0, acc[mt][nt][1] + b1);
                *(__half2*)&Ch[(size_t)(r + 8 + g) * N + c] =
                    __floats2half2_rn(acc[mt][nt][2] + b0, acc[mt][nt][3] + b1);
            } else {
                float* Cf = (float*)Cp;
                Cf[(size_t)(r + g) * N + c]         = acc[mt][nt][0] + b0;
                Cf[(size_t)(r + g) * N + c + 1]     = acc[mt][nt][1] + b1;
                Cf[(size_t)(r + 8 + g) * N + c]     = acc[mt][nt][2] + b0;
                Cf[(size_t)(r + 8 + g) * N + c + 1] = acc[mt][nt][3] + b1;
            }
        }
    }
}

// ---------------------------------------------------------------------------
// Flash attention, all-fp16 inputs, double-buffered K/V, 1 barrier/kv tile.
// Block = (b, h, 128-row Q tile), 8 warps; warp = 16 q-rows x 64 keys x 64 d.
// ---------------------------------------------------------------------------
#define HKP 36

#define SCL2E 0.3606737602222409f   // 0.25 * log2(e)

__global__ __launch_bounds__(256, 2) void attn_tc4(
    const __half* __restrict__ Qh, const __half* __restrict__ Kh,
    const __half* __restrict__ Vh, __half* __restrict__ Ctx)
{
    __shared__ uint32_t sKh[2][64 * HKP];   // half2 K tile [key][dpair]
    __shared__ uint32_t sVb[2][64 * HKP];   // half2 V^T tile [d][keypair]

    const int tid = threadIdx.x;
    const int lane = tid & 31, warp = tid >> 5;
    const int g = lane >> 2, tig = lane & 3;

    const int b = blockIdx.z, h = blockIdx.y, q0 = blockIdx.x * 128;
    const int hd = h * DD;

    // per-thread load geometry
    const int kr = tid >> 3;          // K/Q copy row (per p: +32)
    const int kq = tid & 7;           // uint4 index within row (words kq*4)
    const int vpair = tid & 31;       // V key pair
    const int vdb = (tid >> 5) * 8;   // V d base (8 d per thread)

    // ---- Stage Q (two 64-row halves into sKh[0], sKh[1]), frags to regs ----
#pragma unroll
    for (int hf = 0; hf < 2; hf++) {
#pragma unroll
        for (int p = 0; p < 2; p++) {
            int r = kr + p * 32;
            uint4 v = *(const uint4*)&Qh[(size_t)(b * SS + q0 + hf * 64 + r) * EE + hd + kq * 8];
            sKh[hf][r * HKP + kq * 4 + 0] = v.x;
            sKh[hf][r * HKP + kq * 4 + 1] = v.y;
            sKh[hf][r * HKP + kq * 4 + 2] = v.z;
            sKh[hf][r * HKP + kq * 4 + 3] = v.w;
        }
    }
    __syncthreads();

    uint32_t qa[4][4];
    {
        const uint32_t* sQ = sKh[warp >> 2];
        int rw = (warp & 3) * 16;
#pragma unroll
        for (int kc = 0; kc < 4; kc++) {
            qa[kc][0] = sQ[(rw + g) * HKP + kc * 8 + tig];
            qa[kc][1] = sQ[(rw + 8 + g) * HKP + kc * 8 + tig];
            qa[kc][2] = sQ[(rw + g) * HKP + kc * 8 + tig + 4];
            qa[kc][3] = sQ[(rw + 8 + g) * HKP + kc * 8 + tig + 4];
        }
    }
    __syncthreads();

    float m0 = -INFINITY, m1 = -INFINITY, l0 = 0.0f, l1 = 0.0f;
    float o[8][4];
#pragma unroll
    for (int nt = 0; nt < 8; nt++)
#pragma unroll
        for (int l = 0; l < 4; l++) o[nt][l] = 0.0f;

    uint32_t kst[8], vst[8];

    auto stageKV = [&](int kv0) {
#pragma unroll
        for (int p = 0; p < 2; p++) {
            uint4 v = *(const uint4*)&Kh[(size_t)(b * SS + kv0 + kr + p * 32) * EE + hd + kq * 8];
            kst[4 * p + 0] = v.x; kst[4 * p + 1] = v.y;
            kst[4 * p + 2] = v.z; kst[4 * p + 3] = v.w;
        }
        const __half* vp = &Vh[(size_t)(b * SS + kv0 + 2 * vpair) * EE + hd + vdb];
        uint4 r0 = *(const uint4*)vp;
        uint4 r1 = *(const uint4*)(vp + EE);
        vst[0] = lows2(r0.x, r1.x);  vst[1] = highs2(r0.x, r1.x);
        vst[2] = lows2(r0.y, r1.y);  vst[3] = highs2(r0.y, r1.y);
        vst[4] = lows2(r0.z, r1.z);  vst[5] = highs2(r0.z, r1.z);
        vst[6] = lows2(r0.w, r1.w);  vst[7] = highs2(r0.w, r1.w);
    };
    auto commitKV = [&](int buf) {
#pragma unroll
        for (int p = 0; p < 2; p++) {
            int r = kr + p * 32;
            sKh[buf][r * HKP + kq * 4 + 0] = kst[4 * p + 0];
            sKh[buf][r * HKP + kq * 4 + 1] = kst[4 * p + 1];
            sKh[buf][r * HKP + kq * 4 + 2] = kst[4 * p + 2];
            sKh[buf][r * HKP + kq * 4 + 3] = kst[4 * p + 3];
        }
#pragma unroll
        for (int j = 0; j < 8; j++)
            sVb[buf][(vdb + j) * HKP + vpair] = vst[j];
    };

    stageKV(0);
    commitKV(0);
    __syncthreads();

    for (int t = 0; t < SS / 64; t++) {
        const int bf = t & 1;
        const int kvn = (t + 1) * 64;

        if (kvn < SS) stageKV(kvn);

        const uint32_t* sK = sKh[bf];
        const uint32_t* sV = sVb[bf];

        // ---- S = Q K^T ----
        float sc[8][4];
#pragma unroll
        for (int nt = 0; nt < 8; nt++)
#pragma unroll
            for (int l = 0; l < 4; l++) sc[nt][l] = 0.0f;

#pragma unroll
        for (int kc = 0; kc < 4; kc++) {
#pragma unroll
            for (int nt = 0; nt < 8; nt++) {
                uint32_t bb[2];
                bb[0] = sK[(nt * 8 + g) * HKP + kc * 8 + tig];
                bb[1] = sK[(nt * 8 + g) * HKP + kc * 8 + tig + 4];
                mma16h(sc[nt], qa[kc], bb);
            }
        }

        // ---- online softmax in registers ----
        float mx0 = -INFINITY, mx1 = -INFINITY;
#pragma unroll
        for (int nt = 0; nt < 8; nt++) {
            mx0 = fmaxf(mx0, fmaxf(sc[nt][0], sc[nt][1]));
            mx1 = fmaxf(mx1, fmaxf(sc[nt][2], sc[nt][3]));
        }
        mx0 = fmaxf(mx0, __shfl_xor_sync(0xFFFFFFFFu, mx0, 1));
        mx0 = fmaxf(mx0, __shfl_xor_sync(0xFFFFFFFFu, mx0, 2));
        mx1 = fmaxf(mx1, __shfl_xor_sync(0xFFFFFFFFu, mx1, 1));
        mx1 = fmaxf(mx1, __shfl_xor_sync(0xFFFFFFFFu, mx1, 2));

        float mn0 = fmaxf(m0, mx0 * SCL2E);
        float mn1 = fmaxf(m1, mx1 * SCL2E);
        float al0 = exp2f(m0 - mn0);
        float al1 = exp2f(m1 - mn1);
        m0 = mn0; m1 = mn1;

        float s0 = 0.0f, s1 = 0.0f;
#pragma unroll
        for (int nt = 0; nt < 8; nt++) {
            sc[nt][0] = exp2f(sc[nt][0] * SCL2E - mn0);
            sc[nt][1] = exp2f(sc[nt][1] * SCL2E - mn0);
            sc[nt][2] = exp2f(sc[nt][2] * SCL2E - mn1);
            sc[nt][3] = exp2f(sc[nt][3] * SCL2E - mn1);
            s0 += sc[nt][0] + sc[nt][1];
            s1 += sc[nt][2] + sc[nt][3];
        }
        s0 += __shfl_xor_sync(0xFFFFFFFFu, s0, 1);
        s0 += __shfl_xor_sync(0xFFFFFFFFu, s0, 2);
        s1 += __shfl_xor_sync(0xFFFFFFFFu, s1, 1);
        s1 += __shfl_xor_sync(0xFFFFFFFFu, s1, 2);
        l0 = l0 * al0 + s0;
        l1 = l1 * al1 + s1;

#pragma unroll
        for (int nt = 0; nt < 8; nt++) {
            o[nt][0] *= al0; o[nt][1] *= al0;
            o[nt][2] *= al1; o[nt][3] *= al1;
        }

        // ---- O += P @ V ----
#pragma unroll
        for (int kc = 0; kc < 4; kc++) {
            uint32_t pa[4];
            pa[0] = h2pack(sc[2 * kc][0], sc[2 * kc][1]);
            pa[1] = h2pack(sc[2 * kc][2], sc[2 * kc][3]);
            pa[2] = h2pack(sc[2 * kc + 1][0], sc[2 * kc + 1][1]);
            pa[3] = h2pack(sc[2 * kc + 1][2], sc[2 * kc + 1][3]);
#pragma unroll
            for (int nt = 0; nt < 8; nt++) {
                uint32_t bb[2];
                bb[0] = sV[(nt * 8 + g) * HKP + kc * 8 + tig];
                bb[1] = sV[(nt * 8 + g) * HKP + kc * 8 + tig + 4];
                mma16h(o[nt], pa, bb);
            }
        }

        if (kvn < SS) commitKV(bf ^ 1);
        __syncthreads();
    }

    // ---- Epilogue: half2 stores to Ctx ----
    const float i0 = 1.0f / l0;
    const float i1 = 1.0f / l1;
    const size_t rA = (size_t)(b * SS + q0 + warp * 16 + g) * EE + hd;
    const size_t rB = rA + 8 * (size_t)EE;
#pragma unroll
    for (int nt = 0; nt < 8; nt++) {
        int d = nt * 8 + 2 * tig;
        *(__half2*)&Ctx[rA + d] = __floats2half2_rn(o[nt][0] * i0, o[nt][1] * i0);
        *(__half2*)&Ctx[rB + d] = __floats2half2_rn(o[nt][2] * i1, o[nt][3] * i1);
    }
}

// ---------------------------------------------------------------------------
// Launch
// ---------------------------------------------------------------------------
extern "C" void kernel_launch(void* const* d_in, const int* in_sizes, int n_in,
                              void* d_out, int out_size)
{
    const float* q  = (const float*)d_in[0];
    const float* k  = (const float*)d_in[1];
    const float* v  = (const float*)d_in[2];
    const float* Wq = (const float*)d_in[3];
    const float* bq = (const float*)d_in[4];
    const float* Wk = (const float*)d_in[5];
    const float* bk = (const float*)d_in[6];
    const float* Wv = (const float*)d_in[7];
    const float* bv = (const float*)d_in[8];
    const float* Wo = (const float*)d_in[9];
    const float* bo = (const float*)d_in[10];
    float* out = (float*)d_out;

    __half* Qh;  cudaGetSymbolAddress((void**)&Qh,  g_Qh);
    __half* Kh;  cudaGetSymbolAddress((void**)&Kh,  g_Kh);
    __half* Vh;  cudaGetSymbolAddress((void**)&Vh,  g_Vh);
    __half* Ctx; cudaGetSymbolAddress((void**)&Ctx, g_Ctx);

    dim3 gemm_grid(EE / 128, MTOT / 128);   // (8, 32)
    gemm_h<false, true><<<gemm_grid, 256>>>(q, Wq, bq, Qh);
    gemm_h<false, true><<<gemm_grid, 256>>>(k, Wk, bk, Kh);
    gemm_h<false, true><<<gemm_grid, 256>>>(v, Wv, bv, Vh);

    dim3 attn_grid(SS / 128, HH, BB);       // (16, 16, 2)
    attn_tc4<<<attn_grid, 256>>>(Qh, Kh, Vh, Ctx);

    gemm_h<true, false><<<gemm_grid, 256>>>(Ctx, Wo, bo, out);
}

// round 16
// speedup vs baseline: 6.8361x; 1.1511x over previous
#include <cuda_runtime.h>
#include <cuda_fp16.h>
#include <math.h>
#include <stdint.h>

#define BB 2
#define SS 2048
#define EE 1024
#define HH 16
#define DD 64
#define MTOT (BB * SS)   // 4096

// Scratch in half precision
__device__ __half g_Qh[MTOT * EE];
__device__ __half g_Kh[MTOT * EE];
__device__ __half g_Vh[MTOT * EE];
__device__ __half g_Ctx[MTOT * EE];

// ---------------------------------------------------------------------------
// helpers
// ---------------------------------------------------------------------------
__device__ __forceinline__ void mma16h(float* c, const uint32_t* a, const uint32_t* b) {
    asm volatile(
        "mma.sync.aligned.m16n8k16.row.col.f32.f16.f16.f32 "
        "{%0,%1,%2,%3},{%4,%5,%6,%7},{%8,%9},{%0,%1,%2,%3};"
        : "+f"(c[0]), "+f"(c[1]), "+f"(c[2]), "+f"(c[3])
        : "r"(a[0]), "r"(a[1]), "r"(a[2]), "r"(a[3]), "r"(b[0]), "r"(b[1]));
}

__device__ __forceinline__ uint32_t h2pack(float lo, float hi) {
    __half2 h = __floats2half2_rn(lo, hi);
    return *reinterpret_cast<uint32_t*>(&h);
}

__device__ __forceinline__ uint32_t lows2(uint32_t a, uint32_t b) {
    uint32_t r; asm("prmt.b32 %0, %1, %2, 0x5410;" : "=r"(r) : "r"(a), "r"(b)); return r;
}
__device__ __forceinline__ uint32_t highs2(uint32_t a, uint32_t b) {
    uint32_t r; asm("prmt.b32 %0, %1, %2, 0x7632;" : "=r"(r) : "r"(a), "r"(b)); return r;
}

__device__ __forceinline__ void ldsm4(uint32_t& r0, uint32_t& r1, uint32_t& r2, uint32_t& r3,
                                      uint32_t addr) {
    asm volatile("ldmatrix.sync.aligned.m8n8.x4.shared.b16 {%0,%1,%2,%3}, [%4];"
                 : "=r"(r0), "=r"(r1), "=r"(r2), "=r"(r3) : "r"(addr));
}

__device__ __forceinline__ uint32_t s2u(const void* p) {
    return (uint32_t)__cvta_generic_to_shared(p);
}

// ---------------------------------------------------------------------------
// GEMM body: C[M,N] = A[M,K] @ W[N,K]^T + bias[N], fp16 MMA, double-buffered,
// ldmatrix fragment loads. Block tile 128x128, BK=32, 256 threads.
// ---------------------------------------------------------------------------
#define GSP 20   // smem stride in words (16 data + 4 pad)

template<bool AH, bool CH>
__device__ __forceinline__ void gemm_body(
    const void* __restrict__ Ap, const float* __restrict__ Wp,
    const float* __restrict__ bias, void* __restrict__ Cp,
    uint32_t (*sA)[128 * GSP], uint32_t (*sW)[128 * GSP],
    int row0, int col0)
{
    const int N = EE, K = EE;
    const int tid = threadIdx.x;
    const int lane = tid & 31, warp = tid >> 5;
    const int wm = warp >> 1, wn = warp & 1;
    const int g = lane >> 2, tig = lane & 3;

    const float*  Af  = (const float*)Ap;
    const __half* Ahp = (const __half*)Ap;

    const int rL = tid >> 3;          // float-path row (per p: +32)
    const int cL = (tid & 7) * 4;     // float-path col (floats)
    const int rH = tid >> 2;          // half-path row (per p: +64)
    const int cH = (tid & 3) * 8;     // half-path col (halfs)

    // ldmatrix per-lane address offsets (bytes)
    const int r_a = (lane & 7) + (((lane >> 3) & 1) << 3);
    const uint32_t off_a = (uint32_t)(((r_a + wm * 32) * GSP + (lane >> 4) * 4) * 4);
    const int r_b = (lane & 7) + ((lane >> 4) << 3);
    const uint32_t off_b = (uint32_t)(((r_b + wn * 64) * GSP + ((lane >> 3) & 1) * 4) * 4);

    uint32_t aS[8], wS[8];

    float acc[2][8][4];
#pragma unroll
    for (int i = 0; i < 2; i++)
#pragma unroll
        for (int j = 0; j < 8; j++)
#pragma unroll
            for (int l = 0; l < 4; l++) acc[i][j][l] = 0.0f;

    auto stage = [&](int k0) {
        if (!AH) {
#pragma unroll
            for (int p = 0; p < 4; p++) {
                float4 v = *(const float4*)&Af[(size_t)(row0 + rL + p * 32) * K + k0 + cL];
                aS[2 * p]     = h2pack(v.x, v.y);
                aS[2 * p + 1] = h2pack(v.z, v.w);
            }
        } else {
#pragma unroll
            for (int p = 0; p < 2; p++) {
                uint4 v = *(const uint4*)&Ahp[(size_t)(row0 + rH + p * 64) * K + k0 + cH];
                aS[4 * p + 0] = v.x; aS[4 * p + 1] = v.y;
                aS[4 * p + 2] = v.z; aS[4 * p + 3] = v.w;
            }
        }
#pragma unroll
        for (int p = 0; p < 4; p++) {
            float4 v = *(const float4*)&Wp[(size_t)(col0 + rL + p * 32) * K + k0 + cL];
            wS[2 * p]     = h2pack(v.x, v.y);
            wS[2 * p + 1] = h2pack(v.z, v.w);
        }
    };
    auto commit = [&](int buf) {
        if (!AH) {
#pragma unroll
            for (int p = 0; p < 4; p++) {
                sA[buf][(rL + p * 32) * GSP + (tid & 7) * 2]     = aS[2 * p];
                sA[buf][(rL + p * 32) * GSP + (tid & 7) * 2 + 1] = aS[2 * p + 1];
            }
        } else {
#pragma unroll
            for (int p = 0; p < 2; p++)
#pragma unroll
                for (int j = 0; j < 4; j++)
                    sA[buf][(rH + p * 64) * GSP + (tid & 3) * 4 + j] = aS[4 * p + j];
        }
#pragma unroll
        for (int p = 0; p < 4; p++) {
            sW[buf][(rL + p * 32) * GSP + (tid & 7) * 2]     = wS[2 * p];
            sW[buf][(rL + p * 32) * GSP + (tid & 7) * 2 + 1] = wS[2 * p + 1];
        }
    };

    stage(0);
    commit(0);
    __syncthreads();

    const int NT = K / 32;
    for (int t = 0; t < NT; t++) {
        const int buf = t & 1;
        if (t + 1 < NT) stage((t + 1) * 32);

        const uint32_t aBase = s2u(sA[buf]) + off_a;
        const uint32_t wBase = s2u(sW[buf]) + off_b;

#pragma unroll
        for (int ks = 0; ks < 2; ks++) {
            uint32_t af[2][4];
            ldsm4(af[0][0], af[0][1], af[0][2], af[0][3], aBase + (uint32_t)(ks * 32));
            ldsm4(af[1][0], af[1][1], af[1][2], af[1][3],
                  aBase + (uint32_t)(16 * GSP * 4 + ks * 32));
#pragma unroll
            for (int j = 0; j < 4; j++) {
                uint32_t b0[2], b1[2];
                ldsm4(b0[0], b0[1], b1[0], b1[1],
                      wBase + (uint32_t)((j * 16 * GSP) * 4 + ks * 32));
                mma16h(acc[0][2 * j],     af[0], b0);
                mma16h(acc[1][2 * j],     af[1], b0);
                mma16h(acc[0][2 * j + 1], af[0], b1);
                mma16h(acc[1][2 * j + 1], af[1], b1);
            }
        }

        if (t + 1 < NT) commit(buf ^ 1);
        __syncthreads();
    }

    // ---- epilogue ----
#pragma unroll
    for (int mt = 0; mt < 2; mt++) {
        int r = row0 + wm * 32 + mt * 16;
#pragma unroll
        for (int nt = 0; nt < 8; nt++) {
            int c = col0 + wn * 64 + nt * 8 + 2 * tig;
            float b0 = bias[c], b1 = bias[c + 1];
            if (CH) {
                __half* Ch = (__half*)Cp;
                *(__half2*)&Ch[(size_t)(r + g) * N + c] =
                    __floats2half2_rn(acc[mt][nt][0] + b0, acc[mt][nt][1] + b1);
                *(__half2*)&Ch[(size_t)(r + 8 + g) * N + c] =
                    __floats2half2_rn(acc[mt][nt][2] + b0, acc[mt][nt][3] + b1);
            } else {
                float* Cf = (float*)Cp;
                Cf[(size_t)(r + g) * N + c]         = acc[mt][nt][0] + b0;
                Cf[(size_t)(r + g) * N + c + 1]     = acc[mt][nt][1] + b1;
                Cf[(size_t)(r + 8 + g) * N + c]     = acc[mt][nt][2] + b0;
                Cf[(size_t)(r + 8 + g) * N + c + 1] = acc[mt][nt][3] + b1;
            }
        }
    }
}

// Fused Q/K/V projection: blockIdx.z selects which projection this CTA computes.
__global__ __launch_bounds__(256, 2) void gemm_qkv(
    const float* __restrict__ q, const float* __restrict__ k, const float* __restrict__ v,
    const float* __restrict__ Wq, const float* __restrict__ bq,
    const float* __restrict__ Wk, const float* __restrict__ bk,
    const float* __restrict__ Wv, const float* __restrict__ bv,
    __half* __restrict__ Qh, __half* __restrict__ Kh, __half* __restrict__ Vh)
{
    __shared__ uint32_t sA[2][128 * GSP];
    __shared__ uint32_t sW[2][128 * GSP];
    const float* A; const float* W; const float* bias; __half* C;
    if (blockIdx.z == 0)      { A = q; W = Wq; bias = bq; C = Qh; }
    else if (blockIdx.z == 1) { A = k; W = Wk; bias = bk; C = Kh; }
    else                      { A = v; W = Wv; bias = bv; C = Vh; }
    gemm_body<false, true>(A, W, bias, C, sA, sW, blockIdx.y * 128, blockIdx.x * 128);
}

__global__ __launch_bounds__(256, 2) void gemm_out(
    const __half* __restrict__ Ctx, const float* __restrict__ Wo,
    const float* __restrict__ bo, float* __restrict__ out)
{
    __shared__ uint32_t sA[2][128 * GSP];
    __shared__ uint32_t sW[2][128 * GSP];
    gemm_body<true, false>(Ctx, Wo, bo, out, sA, sW, blockIdx.y * 128, blockIdx.x * 128);
}

// ---------------------------------------------------------------------------
// Flash attention, fp16 MMA + ldmatrix, double-buffered K/V, 1 barrier/tile.
// Block = (b, h, 128-row Q tile), 8 warps; warp = 16 q-rows x 64 keys x 64 d.
// ---------------------------------------------------------------------------
#define HKP 36

#define SCL2E 0.3606737602222409f   // 0.25 * log2(e)

__global__ __launch_bounds__(256, 2) void attn_tc5(
    const __half* __restrict__ Qh, const __half* __restrict__ Kh,
    const __half* __restrict__ Vh, __half* __restrict__ Ctx)
{
    __shared__ uint32_t sKh[2][64 * HKP];   // half2 K tile [key][dpair]
    __shared__ uint32_t sVb[2][64 * HKP];   // half2 V^T tile [d][keypair]

    const int tid = threadIdx.x;
    const int lane = tid & 31, warp = tid >> 5;
    const int g = lane >> 2, tig = lane & 3;

    const int b = blockIdx.z, h = blockIdx.y, q0 = blockIdx.x * 128;
    const int hd = h * DD;

    // per-thread load geometry
    const int kr = tid >> 3;          // K/Q copy row (per p: +32)
    const int kq = tid & 7;           // uint4 index within row
    const int vpair = tid & 31;       // V key pair
    const int vdb = (tid >> 5) * 8;   // V d base

    // ldmatrix per-lane base offset (bytes) for B-side fragments
    const int r_b = (lane & 7) + ((lane >> 4) << 3);
    const uint32_t off_b = (uint32_t)((r_b * HKP + ((lane >> 3) & 1) * 4) * 4);

    // ---- Stage Q (two 64-row halves into sKh[0], sKh[1]), frags to regs ----
#pragma unroll
    for (int hf = 0; hf < 2; hf++) {
#pragma unroll
        for (int p = 0; p < 2; p++) {
            int r = kr + p * 32;
            uint4 v = *(const uint4*)&Qh[(size_t)(b * SS + q0 + hf * 64 + r) * EE + hd + kq * 8];
            sKh[hf][r * HKP + kq * 4 + 0] = v.x;
            sKh[hf][r * HKP + kq * 4 + 1] = v.y;
            sKh[hf][r * HKP + kq * 4 + 2] = v.z;
            sKh[hf][r * HKP + kq * 4 + 3] = v.w;
        }
    }
    __syncthreads();

    uint32_t qa[4][4];
    {
        // A fragment via ldmatrix: rows rw..rw+16, k halfs kc*16..+16
        const int r_a = (lane & 7) + (((lane >> 3) & 1) << 3);
        const uint32_t off_a = (uint32_t)((((warp & 3) * 16 + r_a) * HKP + (lane >> 4) * 4) * 4);
        const uint32_t qBase = s2u(sKh[warp >> 2]) + off_a;
#pragma unroll
        for (int kc = 0; kc < 4; kc++)
            ldsm4(qa[kc][0], qa[kc][1], qa[kc][2], qa[kc][3], qBase + (uint32_t)(kc * 32));
    }
    __syncthreads();

    float m0 = -INFINITY, m1 = -INFINITY, l0 = 0.0f, l1 = 0.0f;
    float o[8][4];
#pragma unroll
    for (int nt = 0; nt < 8; nt++)
#pragma unroll
        for (int l = 0; l < 4; l++) o[nt][l] = 0.0f;

    uint32_t kst[8], vst[8];

    auto stageKV = [&](int kv0) {
#pragma unroll
        for (int p = 0; p < 2; p++) {
            uint4 v = *(const uint4*)&Kh[(size_t)(b * SS + kv0 + kr + p * 32) * EE + hd + kq * 8];
            kst[4 * p + 0] = v.x; kst[4 * p + 1] = v.y;
            kst[4 * p + 2] = v.z; kst[4 * p + 3] = v.w;
        }
        const __half* vp = &Vh[(size_t)(b * SS + kv0 + 2 * vpair) * EE + hd + vdb];
        uint4 r0 = *(const uint4*)vp;
        uint4 r1 = *(const uint4*)(vp + EE);
        vst[0] = lows2(r0.x, r1.x);  vst[1] = highs2(r0.x, r1.x);
        vst[2] = lows2(r0.y, r1.y);  vst[3] = highs2(r0.y, r1.y);
        vst[4] = lows2(r0.z, r1.z);  vst[5] = highs2(r0.z, r1.z);
        vst[6] = lows2(r0.w, r1.w);  vst[7] = highs2(r0.w, r1.w);
    };
    auto commitKV = [&](int buf) {
#pragma unroll
        for (int p = 0; p < 2; p++) {
            int r = kr + p * 32;
            sKh[buf][r * HKP + kq * 4 + 0] = kst[4 * p + 0];
            sKh[buf][r * HKP + kq * 4 + 1] = kst[4 * p + 1];
            sKh[buf][r * HKP + kq * 4 + 2] = kst[4 * p + 2];
            sKh[buf][r * HKP + kq * 4 + 3] = kst[4 * p + 3];
        }
#pragma unroll
        for (int j = 0; j < 8; j++)
            sVb[buf][(vdb + j) * HKP + vpair] = vst[j];
    };

    stageKV(0);
    commitKV(0);
    __syncthreads();

    for (int t = 0; t < SS / 64; t++) {
        const int bf = t & 1;
        const int kvn = (t + 1) * 64;

        if (kvn < SS) stageKV(kvn);

        const uint32_t kBase = s2u(sKh[bf]) + off_b;
        const uint32_t vBase = s2u(sVb[bf]) + off_b;

        // ---- S = Q K^T ----
        float sc[8][4];
#pragma unroll
        for (int nt = 0; nt < 8; nt++)
#pragma unroll
            for (int l = 0; l < 4; l++) sc[nt][l] = 0.0f;

#pragma unroll
        for (int kc = 0; kc < 4; kc++) {
#pragma unroll
            for (int j = 0; j < 4; j++) {
                uint32_t b0[2], b1[2];
                ldsm4(b0[0], b0[1], b1[0], b1[1],
                      kBase + (uint32_t)((j * 16 * HKP) * 4 + kc * 32));
                mma16h(sc[2 * j],     qa[kc], b0);
                mma16h(sc[2 * j + 1], qa[kc], b1);
            }
        }

        // ---- online softmax in registers ----
        float mx0 = -INFINITY, mx1 = -INFINITY;
#pragma unroll
        for (int nt = 0; nt < 8; nt++) {
            mx0 = fmaxf(mx0, fmaxf(sc[nt][0], sc[nt][1]));
            mx1 = fmaxf(mx1, fmaxf(sc[nt][2], sc[nt][3]));
        }
        mx0 = fmaxf(mx0, __shfl_xor_sync(0xFFFFFFFFu, mx0, 1));
        mx0 = fmaxf(mx0, __shfl_xor_sync(0xFFFFFFFFu, mx0, 2));
        mx1 = fmaxf(mx1, __shfl_xor_sync(0xFFFFFFFFu, mx1, 1));
        mx1 = fmaxf(mx1, __shfl_xor_sync(0xFFFFFFFFu, mx1, 2));

        float mn0 = fmaxf(m0, mx0 * SCL2E);
        float mn1 = fmaxf(m1, mx1 * SCL2E);
        float al0 = exp2f(m0 - mn0);
        float al1 = exp2f(m1 - mn1);
        m0 = mn0; m1 = mn1;

        float s0 = 0.0f, s1 = 0.0f;
#pragma unroll
        for (int nt = 0; nt < 8; nt++) {
            sc[nt][0] = exp2f(sc[nt][0] * SCL2E - mn0);
            sc[nt][1] = exp2f(sc[nt][1] * SCL2E - mn0);
            sc[nt][2] = exp2f(sc[nt][2] * SCL2E - mn1);
            sc[nt][3] = exp2f(sc[nt][3] * SCL2E - mn1);
            s0 += sc[nt][0] + sc[nt][1];
            s1 += sc[nt][2] + sc[nt][3];
        }
        s0 += __shfl_xor_sync(0xFFFFFFFFu, s0, 1);
        s0 += __shfl_xor_sync(0xFFFFFFFFu, s0, 2);
        s1 += __shfl_xor_sync(0xFFFFFFFFu, s1, 1);
        s1 += __shfl_xor_sync(0xFFFFFFFFu, s1, 2);
        l0 = l0 * al0 + s0;
        l1 = l1 * al1 + s1;

#pragma unroll
        for (int nt = 0; nt < 8; nt++) {
            o[nt][0] *= al0; o[nt][1] *= al0;
            o[nt][2] *= al1; o[nt][3] *= al1;
        }

        // ---- O += P @ V ----
#pragma unroll
        for (int kc = 0; kc < 4; kc++) {
            uint32_t pa[4];
            pa[0] = h2pack(sc[2 * kc][0], sc[2 * kc][1]);
            pa[1] = h2pack(sc[2 * kc][2], sc[2 * kc][3]);
            pa[2] = h2pack(sc[2 * kc + 1][0], sc[2 * kc + 1][1]);
            pa[3] = h2pack(sc[2 * kc + 1][2], sc[2 * kc + 1][3]);
#pragma unroll
            for (int j = 0; j < 4; j++) {
                uint32_t b0[2], b1[2];
                ldsm4(b0[0], b0[1], b1[0], b1[1],
                      vBase + (uint32_t)((j * 16 * HKP) * 4 + kc * 32));
                mma16h(o[2 * j],     pa, b0);
                mma16h(o[2 * j + 1], pa, b1);
            }
        }

        if (kvn < SS) commitKV(bf ^ 1);
        __syncthreads();
    }

    // ---- Epilogue: half2 stores to Ctx ----
    const float i0 = 1.0f / l0;
    const float i1 = 1.0f / l1;
    const size_t rA = (size_t)(b * SS + q0 + warp * 16 + g) * EE + hd;
    const size_t rB = rA + 8 * (size_t)EE;
#pragma unroll
    for (int nt = 0; nt < 8; nt++) {
        int d = nt * 8 + 2 * tig;
        *(__half2*)&Ctx[rA + d] = __floats2half2_rn(o[nt][0] * i0, o[nt][1] * i0);
        *(__half2*)&Ctx[rB + d] = __floats2half2_rn(o[nt][2] * i1, o[nt][3] * i1);
    }
}

// ---------------------------------------------------------------------------
// Launch
// ---------------------------------------------------------------------------
extern "C" void kernel_launch(void* const* d_in, const int* in_sizes, int n_in,
                              void* d_out, int out_size)
{
    const float* q  = (const float*)d_in[0];
    const float* k  = (const float*)d_in[1];
    const float* v  = (const float*)d_in[2];
    const float* Wq = (const float*)d_in[3];
    const float* bq = (const float*)d_in[4];
    const float* Wk = (const float*)d_in[5];
    const float* bk = (const float*)d_in[6];
    const float* Wv = (const float*)d_in[7];
    const float* bv = (const float*)d_in[8];
    const float* Wo = (const float*)d_in[9];
    const float* bo = (const float*)d_in[10];
    float* out = (float*)d_out;

    __half* Qh;  cudaGetSymbolAddress((void**)&Qh,  g_Qh);
    __half* Kh;  cudaGetSymbolAddress((void**)&Kh,  g_Kh);
    __half* Vh;  cudaGetSymbolAddress((void**)&Vh,  g_Vh);
    __half* Ctx; cudaGetSymbolAddress((void**)&Ctx, g_Ctx);

    dim3 qkv_grid(EE / 128, MTOT / 128, 3);   // (8, 32, 3)
    gemm_qkv<<<qkv_grid, 256>>>(q, k, v, Wq, bq, Wk, bk, Wv, bv, Qh, Kh, Vh);

    dim3 attn_grid(SS / 128, HH, BB);         // (16, 16, 2)
    attn_tc5<<<attn_grid, 256>>>(Qh, Kh, Vh, Ctx);

    dim3 out_grid(EE / 128, MTOT / 128);      // (8, 32)
    gemm_out<<<out_grid, 256>>>(Ctx, Wo, bo, out);
}

// round 17
// speedup vs baseline: 7.0916x; 1.0374x over previous
#include <cuda_runtime.h>
#include <cuda_fp16.h>
#include <math.h>
#include <stdint.h>

#define BB 2
#define SS 2048
#define EE 1024
#define HH 16
#define DD 64
#define MTOT (BB * SS)   // 4096

// Scratch
__device__ __half g_Qh[MTOT * EE];
__device__ __half g_Kh[MTOT * EE];
__device__ __half g_Vh[MTOT * EE];
__device__ __half g_Ctx[MTOT * EE];
// pre-halved inputs and weights
__device__ __half g_Qin[MTOT * EE];
__device__ __half g_Kin[MTOT * EE];
__device__ __half g_Vin[MTOT * EE];
__device__ __half g_Wq[EE * EE];
__device__ __half g_Wk[EE * EE];
__device__ __half g_Wv[EE * EE];
__device__ __half g_Wo[EE * EE];

// ---------------------------------------------------------------------------
// helpers
// ---------------------------------------------------------------------------
__device__ __forceinline__ void mma16h(float* c, const uint32_t* a, const uint32_t* b) {
    asm volatile(
        "mma.sync.aligned.m16n8k16.row.col.f32.f16.f16.f32 "
        "{%0,%1,%2,%3},{%4,%5,%6,%7},{%8,%9},{%0,%1,%2,%3};"
        : "+f"(c[0]), "+f"(c[1]), "+f"(c[2]), "+f"(c[3])
        : "r"(a[0]), "r"(a[1]), "r"(a[2]), "r"(a[3]), "r"(b[0]), "r"(b[1]));
}

__device__ __forceinline__ uint32_t h2pack(float lo, float hi) {
    __half2 h = __floats2half2_rn(lo, hi);
    return *reinterpret_cast<uint32_t*>(&h);
}

__device__ __forceinline__ uint32_t lows2(uint32_t a, uint32_t b) {
    uint32_t r; asm("prmt.b32 %0, %1, %2, 0x5410;" : "=r"(r) : "r"(a), "r"(b)); return r;
}
__device__ __forceinline__ uint32_t highs2(uint32_t a, uint32_t b) {
    uint32_t r; asm("prmt.b32 %0, %1, %2, 0x7632;" : "=r"(r) : "r"(a), "r"(b)); return r;
}

__device__ __forceinline__ void ldsm4(uint32_t& r0, uint32_t& r1, uint32_t& r2, uint32_t& r3,
                                      uint32_t addr) {
    asm volatile("ldmatrix.sync.aligned.m8n8.x4.shared.b16 {%0,%1,%2,%3}, [%4];"
                 : "=r"(r0), "=r"(r1), "=r"(r2), "=r"(r3) : "r"(addr));
}

__device__ __forceinline__ uint32_t s2u(const void* p) {
    return (uint32_t)__cvta_generic_to_shared(p);
}

__device__ __forceinline__ void cpa16(uint32_t dst, const void* src) {
    asm volatile("cp.async.ca.shared.global [%0], [%1], 16;" :: "r"(dst), "l"(src));
}
__device__ __forceinline__ void cpa_commit() {
    asm volatile("cp.async.commit_group;");
}
__device__ __forceinline__ void cpa_wait0() {
    asm volatile("cp.async.wait_group 0;");
}

// ---------------------------------------------------------------------------
// Prep: float -> half conversion
// ---------------------------------------------------------------------------
__global__ __launch_bounds__(256) void prep_inputs(
    const float* __restrict__ q, const float* __restrict__ k, const float* __restrict__ v)
{
    const float* s;
    __half* d;
    if (blockIdx.z == 0)      { s = q; d = g_Qin; }
    else if (blockIdx.z == 1) { s = k; d = g_Kin; }
    else                      { s = v; d = g_Vin; }
    int i = (blockIdx.x * 256 + threadIdx.x) * 4;
    float4 t = *(const float4*)&s[i];
    uint2 o;
    o.x = h2pack(t.x, t.y);
    o.y = h2pack(t.z, t.w);
    *(uint2*)&d[i] = o;
}

__global__ __launch_bounds__(256) void prep_weights(
    const float* __restrict__ wq, const float* __restrict__ wk,
    const float* __restrict__ wv, const float* __restrict__ wo)
{
    const float* s;
    __half* d;
    if (blockIdx.z == 0)      { s = wq; d = g_Wq; }
    else if (blockIdx.z == 1) { s = wk; d = g_Wk; }
    else if (blockIdx.z == 2) { s = wv; d = g_Wv; }
    else                      { s = wo; d = g_Wo; }
    int i = (blockIdx.x * 256 + threadIdx.x) * 4;
    float4 t = *(const float4*)&s[i];
    uint2 o;
    o.x = h2pack(t.x, t.y);
    o.y = h2pack(t.z, t.w);
    *(uint2*)&d[i] = o;
}

// ---------------------------------------------------------------------------
// GEMM body: C[M,N] = A[M,K] @ W[N,K]^T + bias[N], all-fp16 in, cp.async
// double-buffered, ldmatrix. Block tile 128x128, BK=32, 256 threads.
// ---------------------------------------------------------------------------
#define GSP 20   // smem stride in words (16 data + 4 pad); row = 80B (16B-aligned)

template<bool CH>
__device__ __forceinline__ void gemm_body(
    const __half* __restrict__ A, const __half* __restrict__ W,
    const float* __restrict__ bias, void* __restrict__ Cp,
    uint32_t (*sA)[128 * GSP], uint32_t (*sW)[128 * GSP],
    int row0, int col0)
{
    const int N = EE, K = EE;
    const int tid = threadIdx.x;
    const int lane = tid & 31, warp = tid >> 5;
    const int wm = warp >> 1, wn = warp & 1;
    const int g = lane >> 2, tig = lane & 3;

    // cp.async geometry: 128 rows x 2 chunks(16B) per matrix = 512 chunks, 2/thread
    const int ar = tid >> 2;          // row (+64 per p)
    const int ach = tid & 3;          // 16B chunk in row (4 chunks of 8 halfs)

    // ldmatrix per-lane address offsets (bytes)
    const int r_a = (lane & 7) + (((lane >> 3) & 1) << 3);
    const uint32_t off_a = (uint32_t)(((r_a + wm * 32) * GSP + (lane >> 4) * 4) * 4);
    const int r_b = (lane & 7) + ((lane >> 4) << 3);
    const uint32_t off_b = (uint32_t)(((r_b + wn * 64) * GSP + ((lane >> 3) & 1) * 4) * 4);

    const uint32_t sAu[2] = { s2u(sA[0]), s2u(sA[1]) };
    const uint32_t sWu[2] = { s2u(sW[0]), s2u(sW[1]) };

    float acc[2][8][4];
#pragma unroll
    for (int i = 0; i < 2; i++)
#pragma unroll
        for (int j = 0; j < 8; j++)
#pragma unroll
            for (int l = 0; l < 4; l++) acc[i][j][l] = 0.0f;

    auto issue = [&](int k0, int buf) {
#pragma unroll
        for (int p = 0; p < 2; p++) {
            int r = ar + p * 64;
            uint32_t doff = (uint32_t)((r * GSP + ach * 4) * 4);
            cpa16(sAu[buf] + doff, &A[(size_t)(row0 + r) * K + k0 + ach * 8]);
            cpa16(sWu[buf] + doff, &W[(size_t)(col0 + r) * K + k0 + ach * 8]);
        }
        cpa_commit();
    };

    issue(0, 0);
    cpa_wait0();
    __syncthreads();

    const int NT = K / 32;
    for (int t = 0; t < NT; t++) {
        const int buf = t & 1;
        if (t + 1 < NT) issue((t + 1) * 32, buf ^ 1);

        const uint32_t aBase = sAu[buf] + off_a;
        const uint32_t wBase = sWu[buf] + off_b;

#pragma unroll
        for (int ks = 0; ks < 2; ks++) {
            uint32_t af[2][4];
            ldsm4(af[0][0], af[0][1], af[0][2], af[0][3], aBase + (uint32_t)(ks * 32));
            ldsm4(af[1][0], af[1][1], af[1][2], af[1][3],
                  aBase + (uint32_t)(16 * GSP * 4 + ks * 32));
#pragma unroll
            for (int j = 0; j < 4; j++) {
                uint32_t b0[2], b1[2];
                ldsm4(b0[0], b0[1], b1[0], b1[1],
                      wBase + (uint32_t)((j * 16 * GSP) * 4 + ks * 32));
                mma16h(acc[0][2 * j],     af[0], b0);
                mma16h(acc[1][2 * j],     af[1], b0);
                mma16h(acc[0][2 * j + 1], af[0], b1);
                mma16h(acc[1][2 * j + 1], af[1], b1);
            }
        }

        if (t + 1 < NT) cpa_wait0();
        __syncthreads();
    }

    // ---- epilogue ----
#pragma unroll
    for (int mt = 0; mt < 2; mt++) {
        int r = row0 + wm * 32 + mt * 16;
#pragma unroll
        for (int nt = 0; nt < 8; nt++) {
            int c = col0 + wn * 64 + nt * 8 + 2 * tig;
            float b0 = bias[c], b1 = bias[c + 1];
            if (CH) {
                __half* Ch = (__half*)Cp;
                *(__half2*)&Ch[(size_t)(r + g) * N + c] =
                    __floats2half2_rn(acc[mt][nt][0] + b0, acc[mt][nt][1] + b1);
                *(__half2*)&Ch[(size_t)(r + 8 + g) * N + c] =
                    __floats2half2_rn(acc[mt][nt][2] + b0, acc[mt][nt][3] + b1);
            } else {
                float* Cf = (float*)Cp;
                Cf[(size_t)(r + g) * N + c]         = acc[mt][nt][0] + b0;
                Cf[(size_t)(r + g) * N + c + 1]     = acc[mt][nt][1] + b1;
                Cf[(size_t)(r + 8 + g) * N + c]     = acc[mt][nt][2] + b0;
                Cf[(size_t)(r + 8 + g) * N + c + 1] = acc[mt][nt][3] + b1;
            }
        }
    }
}

// Fused Q/K/V projection
__global__ __launch_bounds__(256, 2) void gemm_qkv(
    const float* __restrict__ bq, const float* __restrict__ bk,
    const float* __restrict__ bv)
{
    __shared__ uint32_t sA[2][128 * GSP];
    __shared__ uint32_t sW[2][128 * GSP];
    const __half* A; const __half* W; const float* bias; __half* C;
    if (blockIdx.z == 0)      { A = g_Qin; W = g_Wq; bias = bq; C = g_Qh; }
    else if (blockIdx.z == 1) { A = g_Kin; W = g_Wk; bias = bk; C = g_Kh; }
    else                      { A = g_Vin; W = g_Wv; bias = bv; C = g_Vh; }
    gemm_body<true>(A, W, bias, C, sA, sW, blockIdx.y * 128, blockIdx.x * 128);
}

__global__ __launch_bounds__(256, 2) void gemm_out(
    const float* __restrict__ bo, float* __restrict__ out)
{
    __shared__ uint32_t sA[2][128 * GSP];
    __shared__ uint32_t sW[2][128 * GSP];
    gemm_body<false>(g_Ctx, g_Wo, bo, out, sA, sW, blockIdx.y * 128, blockIdx.x * 128);
}

// ---------------------------------------------------------------------------
// Flash attention, fp16 MMA + ldmatrix, double-buffered K/V, 1 barrier/tile.
// (unchanged from R16)
// ---------------------------------------------------------------------------
#define HKP 36

#define SCL2E 0.3606737602222409f   // 0.25 * log2(e)

__global__ __launch_bounds__(256, 2) void attn_tc5(
    const __half* __restrict__ Qh, const __half* __restrict__ Kh,
    const __half* __restrict__ Vh, __half* __restrict__ Ctx)
{
    __shared__ uint32_t sKh[2][64 * HKP];   // half2 K tile [key][dpair]
    __shared__ uint32_t sVb[2][64 * HKP];   // half2 V^T tile [d][keypair]

    const int tid = threadIdx.x;
    const int lane = tid & 31, warp = tid >> 5;
    const int g = lane >> 2, tig = lane & 3;

    const int b = blockIdx.z, h = blockIdx.y, q0 = blockIdx.x * 128;
    const int hd = h * DD;

    const int kr = tid >> 3;
    const int kq = tid & 7;
    const int vpair = tid & 31;
    const int vdb = (tid >> 5) * 8;

    const int r_b = (lane & 7) + ((lane >> 4) << 3);
    const uint32_t off_b = (uint32_t)((r_b * HKP + ((lane >> 3) & 1) * 4) * 4);

    // ---- Stage Q ----
#pragma unroll
    for (int hf = 0; hf < 2; hf++) {
#pragma unroll
        for (int p = 0; p < 2; p++) {
            int r = kr + p * 32;
            uint4 v = *(const uint4*)&Qh[(size_t)(b * SS + q0 + hf * 64 + r) * EE + hd + kq * 8];
            sKh[hf][r * HKP + kq * 4 + 0] = v.x;
            sKh[hf][r * HKP + kq * 4 + 1] = v.y;
            sKh[hf][r * HKP + kq * 4 + 2] = v.z;
            sKh[hf][r * HKP + kq * 4 + 3] = v.w;
        }
    }
    __syncthreads();

    uint32_t qa[4][4];
    {
        const int r_a = (lane & 7) + (((lane >> 3) & 1) << 3);
        const uint32_t off_a = (uint32_t)((((warp & 3) * 16 + r_a) * HKP + (lane >> 4) * 4) * 4);
        const uint32_t qBase = s2u(sKh[warp >> 2]) + off_a;
#pragma unroll
        for (int kc = 0; kc < 4; kc++)
            ldsm4(qa[kc][0], qa[kc][1], qa[kc][2], qa[kc][3], qBase + (uint32_t)(kc * 32));
    }
    __syncthreads();

    float m0 = -INFINITY, m1 = -INFINITY, l0 = 0.0f, l1 = 0.0f;
    float o[8][4];
#pragma unroll
    for (int nt = 0; nt < 8; nt++)
#pragma unroll
        for (int l = 0; l < 4; l++) o[nt][l] = 0.0f;

    uint32_t kst[8], vst[8];

    auto stageKV = [&](int kv0) {
#pragma unroll
        for (int p = 0; p < 2; p++) {
            uint4 v = *(const uint4*)&Kh[(size_t)(b * SS + kv0 + kr + p * 32) * EE + hd + kq * 8];
            kst[4 * p + 0] = v.x; kst[4 * p + 1] = v.y;
            kst[4 * p + 2] = v.z; kst[4 * p + 3] = v.w;
        }
        const __half* vp = &Vh[(size_t)(b * SS + kv0 + 2 * vpair) * EE + hd + vdb];
        uint4 r0 = *(const uint4*)vp;
        uint4 r1 = *(const uint4*)(vp + EE);
        vst[0] = lows2(r0.x, r1.x);  vst[1] = highs2(r0.x, r1.x);
        vst[2] = lows2(r0.y, r1.y);  vst[3] = highs2(r0.y, r1.y);
        vst[4] = lows2(r0.z, r1.z);  vst[5] = highs2(r0.z, r1.z);
        vst[6] = lows2(r0.w, r1.w);  vst[7] = highs2(r0.w, r1.w);
    };
    auto commitKV = [&](int buf) {
#pragma unroll
        for (int p = 0; p < 2; p++) {
            int r = kr + p * 32;
            sKh[buf][r * HKP + kq * 4 + 0] = kst[4 * p + 0];
            sKh[buf][r * HKP + kq * 4 + 1] = kst[4 * p + 1];
            sKh[buf][r * HKP + kq * 4 + 2] = kst[4 * p + 2];
            sKh[buf][r * HKP + kq * 4 + 3] = kst[4 * p + 3];
        }
#pragma unroll
        for (int j = 0; j < 8; j++)
            sVb[buf][(vdb + j) * HKP + vpair] = vst[j];
    };

    stageKV(0);
    commitKV(0);
    __syncthreads();

    for (int t = 0; t < SS / 64; t++) {
        const int bf = t & 1;
        const int kvn = (t + 1) * 64;

        if (kvn < SS) stageKV(kvn);

        const uint32_t kBase = s2u(sKh[bf]) + off_b;
        const uint32_t vBase = s2u(sVb[bf]) + off_b;

        float sc[8][4];
#pragma unroll
        for (int nt = 0; nt < 8; nt++)
#pragma unroll
            for (int l = 0; l < 4; l++) sc[nt][l] = 0.0f;

#pragma unroll
        for (int kc = 0; kc < 4; kc++) {
#pragma unroll
            for (int j = 0; j < 4; j++) {
                uint32_t b0[2], b1[2];
                ldsm4(b0[0], b0[1], b1[0], b1[1],
                      kBase + (uint32_t)((j * 16 * HKP) * 4 + kc * 32));
                mma16h(sc[2 * j],     qa[kc], b0);
                mma16h(sc[2 * j + 1], qa[kc], b1);
            }
        }

        float mx0 = -INFINITY, mx1 = -INFINITY;
#pragma unroll
        for (int nt = 0; nt < 8; nt++) {
            mx0 = fmaxf(mx0, fmaxf(sc[nt][0], sc[nt][1]));
            mx1 = fmaxf(mx1, fmaxf(sc[nt][2], sc[nt][3]));
        }
        mx0 = fmaxf(mx0, __shfl_xor_sync(0xFFFFFFFFu, mx0, 1));
        mx0 = fmaxf(mx0, __shfl_xor_sync(0xFFFFFFFFu, mx0, 2));
        mx1 = fmaxf(mx1, __shfl_xor_sync(0xFFFFFFFFu, mx1, 1));
        mx1 = fmaxf(mx1, __shfl_xor_sync(0xFFFFFFFFu, mx1, 2));

        float mn0 = fmaxf(m0, mx0 * SCL2E);
        float mn1 = fmaxf(m1, mx1 * SCL2E);
        float al0 = exp2f(m0 - mn0);
        float al1 = exp2f(m1 - mn1);
        m0 = mn0; m1 = mn1;

        float s0 = 0.0f, s1 = 0.0f;
#pragma unroll
        for (int nt = 0; nt < 8; nt++) {
            sc[nt][0] = exp2f(sc[nt][0] * SCL2E - mn0);
            sc[nt][1] = exp2f(sc[nt][1] * SCL2E - mn0);
            sc[nt][2] = exp2f(sc[nt][2] * SCL2E - mn1);
            sc[nt][3] = exp2f(sc[nt][3] * SCL2E - mn1);
            s0 += sc[nt][0] + sc[nt][1];
            s1 += sc[nt][2] + sc[nt][3];
        }
        s0 += __shfl_xor_sync(0xFFFFFFFFu, s0, 1);
        s0 += __shfl_xor_sync(0xFFFFFFFFu, s0, 2);
        s1 += __shfl_xor_sync(0xFFFFFFFFu, s1, 1);
        s1 += __shfl_xor_sync(0xFFFFFFFFu, s1, 2);
        l0 = l0 * al0 + s0;
        l1 = l1 * al1 + s1;

#pragma unroll
        for (int nt = 0; nt < 8; nt++) {
            o[nt][0] *= al0; o[nt][1] *= al0;
            o[nt][2] *= al1; o[nt][3] *= al1;
        }

#pragma unroll
        for (int kc = 0; kc < 4; kc++) {
            uint32_t pa[4];
            pa[0] = h2pack(sc[2 * kc][0], sc[2 * kc][1]);
            pa[1] = h2pack(sc[2 * kc][2], sc[2 * kc][3]);
            pa[2] = h2pack(sc[2 * kc + 1][0], sc[2 * kc + 1][1]);
            pa[3] = h2pack(sc[2 * kc + 1][2], sc[2 * kc + 1][3]);
#pragma unroll
            for (int j = 0; j < 4; j++) {
                uint32_t b0[2], b1[2];
                ldsm4(b0[0], b0[1], b1[0], b1[1],
                      vBase + (uint32_t)((j * 16 * HKP) * 4 + kc * 32));
                mma16h(o[2 * j],     pa, b0);
                mma16h(o[2 * j + 1], pa, b1);
            }
        }

        if (kvn < SS) commitKV(bf ^ 1);
        __syncthreads();
    }

    const float i0 = 1.0f / l0;
    const float i1 = 1.0f / l1;
    const size_t rA = (size_t)(b * SS + q0 + warp * 16 + g) * EE + hd;
    const size_t rB = rA + 8 * (size_t)EE;
#pragma unroll
    for (int nt = 0; nt < 8; nt++) {
        int d = nt * 8 + 2 * tig;
        *(__half2*)&Ctx[rA + d] = __floats2half2_rn(o[nt][0] * i0, o[nt][1] * i0);
        *(__half2*)&Ctx[rB + d] = __floats2half2_rn(o[nt][2] * i1, o[nt][3] * i1);
    }
}

// ---------------------------------------------------------------------------
// Launch
// ---------------------------------------------------------------------------
extern "C" void kernel_launch(void* const* d_in, const int* in_sizes, int n_in,
                              void* d_out, int out_size)
{
    const float* q  = (const float*)d_in[0];
    const float* k  = (const float*)d_in[1];
    const float* v  = (const float*)d_in[2];
    const float* Wq = (const float*)d_in[3];
    const float* bq = (const float*)d_in[4];
    const float* Wk = (const float*)d_in[5];
    const float* bk = (const float*)d_in[6];
    const float* Wv = (const float*)d_in[7];
    const float* bv = (const float*)d_in[8];
    const float* Wo = (const float*)d_in[9];
    const float* bo = (const float*)d_in[10];
    float* out = (float*)d_out;

    __half* Qh;  cudaGetSymbolAddress((void**)&Qh,  g_Qh);
    __half* Kh;  cudaGetSymbolAddress((void**)&Kh,  g_Kh);
    __half* Vh;  cudaGetSymbolAddress((void**)&Vh,  g_Vh);
    __half* Ctx; cudaGetSymbolAddress((void**)&Ctx, g_Ctx);

    // prep: float -> half (inputs: 4096x1024 each; weights: 1024x1024 each)
    dim3 pin_grid(MTOT * EE / (256 * 4), 1, 3);   // (4096, 1, 3)
    prep_inputs<<<pin_grid, 256>>>(q, k, v);
    dim3 pw_grid(EE * EE / (256 * 4), 1, 4);      // (1024, 1, 4)
    prep_weights<<<pw_grid, 256>>>(Wq, Wk, Wv, Wo);

    dim3 qkv_grid(EE / 128, MTOT / 128, 3);       // (8, 32, 3)
    gemm_qkv<<<qkv_grid, 256>>>(bq, bk, bv);

    dim3 attn_grid(SS / 128, HH, BB);             // (16, 16, 2)
    attn_tc5<<<attn_grid, 256>>>(Qh, Kh, Vh, Ctx);

    dim3 out_grid(EE / 128, MTOT / 128);          // (8, 32)
    gemm_out<<<out_grid, 256>>>(bo, out);
}